// round 14
// baseline (speedup 1.0000x reference)
#include <cuda_runtime.h>
#include <cuda_fp16.h>
#include <stdint.h>
#include <math.h>

// ---------------- problem constants ----------------
#define Bb   2
#define Ll   1024
#define HIDv 1024
#define NHh  4
#define DKk  256
#define NCc  32
#define CHh  32
#define BLr  2048
#define GHh  512

extern __shared__ char dynsm[];

// ---------------- scratch ----------------
__device__ float g_qkvlin[BLr * 3 * HIDv];
__device__ float g_beta[BLr * NHh];
__device__ float g_qn[BLr * HIDv];
__device__ float g_kn[BLr * HIDv];
__device__ float g_u[BLr * HIDv];
__device__ float g_w[BLr * HIDv];
__device__ float g_attn[Bb * NHh * NCc * CHh * CHh];
__device__ float g_P[BLr * NHh * 4 * DKk];
__device__ float g_ssum[12 * GHh];
__device__ float g_hid1[BLr * GHh];
__device__ float g_bpart[BLr * NHh * GHh];

__device__ __half g_xh[BLr * HIDv];
__device__ __half g_Ph[BLr * NHh * 4 * DKk];
__device__ __half g_oh[BLr * HIDv];
__device__ __half g_Wqkvh[3 * HIDv * HIDv];
__device__ __half g_Woh[HIDv * HIDv];
__device__ __half g_g1ah[GHh * HIDv];
__device__ __half g_g1bh[GHh * HIDv];

// ---------------- PTX helpers ----------------
__device__ __forceinline__ uint32_t smem_u32(const void* p) {
    uint32_t a;
    asm("{ .reg .u64 t; cvta.to.shared.u64 t, %1; cvt.u32.u64 %0, t; }" : "=r"(a) : "l"(p));
    return a;
}
__device__ __forceinline__ void ldsm_x4(uint32_t* r, uint32_t addr) {
    asm volatile("ldmatrix.sync.aligned.m8n8.x4.shared.b16 {%0,%1,%2,%3}, [%4];"
                 : "=r"(r[0]), "=r"(r[1]), "=r"(r[2]), "=r"(r[3]) : "r"(addr));
}
__device__ __forceinline__ void mma16816h(float* d, const uint32_t* a, const uint32_t* b) {
    asm volatile(
        "mma.sync.aligned.m16n8k16.row.col.f32.f16.f16.f32 "
        "{%0,%1,%2,%3}, {%4,%5,%6,%7}, {%8,%9}, {%0,%1,%2,%3};"
        : "+f"(d[0]), "+f"(d[1]), "+f"(d[2]), "+f"(d[3])
        : "r"(a[0]), "r"(a[1]), "r"(a[2]), "r"(a[3]), "r"(b[0]), "r"(b[1]));
}
__device__ __forceinline__ float f4c(const float4& v, int j) {
    return j == 0 ? v.x : j == 1 ? v.y : j == 2 ? v.z : v.w;
}
__device__ __forceinline__ float silu(float z) {
    return z / (1.f + expf(-z));
}

// ---------------- single-term fp16 HMMA GEMM (R12-proven) ----------------
#define LDAh 40
#define TILEA (128 * LDAh * 2)
#define TILEBB (256 * LDAh * 2)
#define STAGEB (TILEA + TILEBB)
#define GEMM_SMEM (2 * STAGEB)

__global__ __launch_bounds__(256, 1) void gemm_fp16(
    const __half* __restrict__ A, const __half* __restrict__ B,
    float* __restrict__ C, int M, int N, int K) {
    char* smc = dynsm;
    uint32_t sbase = smem_u32(smc);
    int t = threadIdx.x;
    int lane = t & 31;
    int wid = t >> 5;
    int wm = wid & 1;
    int wn = wid >> 1;
    int m0 = blockIdx.y * 128;
    int n0 = blockIdx.x * 256;

    float acc[4][8][4];
#pragma unroll
    for (int i = 0; i < 4; i++)
#pragma unroll
        for (int j = 0; j < 8; j++)
#pragma unroll
            for (int c = 0; c < 4; c++) acc[i][j][c] = 0.f;

    uint4 rg[6];
    int ldrow = t >> 2;
    int ldq = t & 3;
    int soffA0 = ((ldrow)      * LDAh + ldq * 8) * 2;
    int soffA1 = ((ldrow + 64) * LDAh + ldq * 8) * 2;

    int a_off = ((wm * 64 + (lane & 15)) * LDAh + ((lane >> 4) << 3)) * 2;
    int b_off = ((wn * 64 + (lane & 7) + ((lane >> 4) << 3)) * LDAh + (((lane >> 3) & 1) << 3)) * 2;

    const int S = K / 32;

    {
        rg[0] = *(const uint4*)(A + (size_t)(m0 + ldrow) * K + ldq * 8);
        rg[1] = *(const uint4*)(A + (size_t)(m0 + ldrow + 64) * K + ldq * 8);
#pragma unroll
        for (int i = 0; i < 4; i++)
            rg[2 + i] = *(const uint4*)(B + (size_t)(n0 + ldrow + i * 64) * K + ldq * 8);
    }
    *(uint4*)(smc + soffA0) = rg[0];
    *(uint4*)(smc + soffA1) = rg[1];
#pragma unroll
    for (int i = 0; i < 4; i++)
        *(uint4*)(smc + TILEA + ((ldrow + i * 64) * LDAh + ldq * 8) * 2) = rg[2 + i];
    __syncthreads();

    for (int s = 0; s < S; s++) {
        int cur = s & 1;
        if (s + 1 < S) {
            int k0 = (s + 1) * 32;
            rg[0] = *(const uint4*)(A + (size_t)(m0 + ldrow) * K + k0 + ldq * 8);
            rg[1] = *(const uint4*)(A + (size_t)(m0 + ldrow + 64) * K + k0 + ldq * 8);
#pragma unroll
            for (int i = 0; i < 4; i++)
                rg[2 + i] = *(const uint4*)(B + (size_t)(n0 + ldrow + i * 64) * K + k0 + ldq * 8);
        }

        uint32_t sb = sbase + cur * STAGEB;
#pragma unroll
        for (int kk = 0; kk < 32; kk += 16) {
            uint32_t ah[4][4], bf[4][4];
#pragma unroll
            for (int mi = 0; mi < 4; mi++)
                ldsm_x4(ah[mi], sb + a_off + mi * 16 * LDAh * 2 + kk * 2);
#pragma unroll
            for (int nb = 0; nb < 4; nb++)
                ldsm_x4(bf[nb], sb + TILEA + b_off + nb * 16 * LDAh * 2 + kk * 2);
#pragma unroll
            for (int mi = 0; mi < 4; mi++)
#pragma unroll
                for (int nb = 0; nb < 4; nb++) {
                    mma16816h(acc[mi][nb * 2 + 0], ah[mi], &bf[nb][0]);
                    mma16816h(acc[mi][nb * 2 + 1], ah[mi], &bf[nb][2]);
                }
        }

        if (s + 1 < S) {
            char* bb = smc + ((s + 1) & 1) * STAGEB;
            *(uint4*)(bb + soffA0) = rg[0];
            *(uint4*)(bb + soffA1) = rg[1];
#pragma unroll
            for (int i = 0; i < 4; i++)
                *(uint4*)(bb + TILEA + ((ldrow + i * 64) * LDAh + ldq * 8) * 2) = rg[2 + i];
        }
        __syncthreads();
    }

    int frow = lane >> 2;
    int fcol = (lane & 3) * 2;
#pragma unroll
    for (int mi = 0; mi < 4; mi++) {
#pragma unroll
        for (int ni = 0; ni < 8; ni++) {
            int row = m0 + wm * 64 + mi * 16 + frow;
            int col = n0 + wn * 64 + ni * 8 + fcol;
            *(float2*)(C + (size_t)row * N + col) = make_float2(acc[mi][ni][0], acc[mi][ni][1]);
            *(float2*)(C + (size_t)(row + 8) * N + col) = make_float2(acc[mi][ni][2], acc[mi][ni][3]);
        }
    }
}

// ---------------- beta = sigmoid(x @ Wb) + x -> fp16 ----------------
__global__ void beta_xh_kernel(const float* __restrict__ x, const float* __restrict__ Wb) {
    int gw   = (blockIdx.x << 3) + (threadIdx.x >> 5);
    int lane = threadIdx.x & 31;
    const float* xr = x + (size_t)gw * HIDv;
    __half* xhr = g_xh + (size_t)gw * HIDv;
    float a0 = 0.f, a1 = 0.f, a2 = 0.f, a3 = 0.f;
    for (int r = lane; r < HIDv; r += 32) {
        float xv = xr[r];
        xhr[r] = __float2half(xv);
        const float* wb = Wb + r * 4;
        a0 += xv * wb[0]; a1 += xv * wb[1]; a2 += xv * wb[2]; a3 += xv * wb[3];
    }
    for (int o = 16; o; o >>= 1) {
        a0 += __shfl_xor_sync(0xffffffffu, a0, o);
        a1 += __shfl_xor_sync(0xffffffffu, a1, o);
        a2 += __shfl_xor_sync(0xffffffffu, a2, o);
        a3 += __shfl_xor_sync(0xffffffffu, a3, o);
    }
    if (!lane) {
        float* bp = &g_beta[gw * 4];
        bp[0] = 1.f / (1.f + expf(-a0));
        bp[1] = 1.f / (1.f + expf(-a1));
        bp[2] = 1.f / (1.f + expf(-a2));
        bp[3] = 1.f / (1.f + expf(-a3));
    }
}

// src [K][N] fp32 -> dst [N][K] fp16; 2-way z select (g1a/g1b)
__global__ void htrans2_kernel(const float* __restrict__ s0, const float* __restrict__ s1,
                               __half* __restrict__ h0, __half* __restrict__ h1,
                               int K, int N) {
    __shared__ float tile[32][33];
    int z = blockIdx.z;
    const float* src = z ? s1 : s0;
    __half* hi = z ? h1 : h0;
    int k0 = blockIdx.y * 32;
    int n0 = blockIdx.x * 32;
    int tx = threadIdx.x & 31;
    int ty = threadIdx.x >> 5;
    for (int r = ty; r < 32; r += 8) tile[r][tx] = src[(size_t)(k0 + r) * N + n0 + tx];
    __syncthreads();
    for (int r = ty; r < 32; r += 8)
        hi[(size_t)(n0 + r) * K + k0 + tx] = __float2half(tile[tx][r]);
}

// 4 fused 1024x1024 weight transposes
__global__ void htrans4_kernel(const float* __restrict__ s0, const float* __restrict__ s1,
                               const float* __restrict__ s2, const float* __restrict__ s3,
                               __half* __restrict__ h0, __half* __restrict__ h1,
                               __half* __restrict__ h2, __half* __restrict__ h3) {
    __shared__ float tile[32][33];
    int z = blockIdx.z;
    const float* src = (z == 0) ? s0 : (z == 1) ? s1 : (z == 2) ? s2 : s3;
    __half* hi = (z == 0) ? h0 : (z == 1) ? h1 : (z == 2) ? h2 : h3;
    int k0 = blockIdx.y * 32;
    int n0 = blockIdx.x * 32;
    int tx = threadIdx.x & 31;
    int ty = threadIdx.x >> 5;
    for (int r = ty; r < 32; r += 8) tile[r][tx] = src[(size_t)(k0 + r) * 1024 + n0 + tx];
    __syncthreads();
    for (int r = ty; r < 32; r += 8)
        hi[(size_t)(n0 + r) * 1024 + k0 + tx] = __float2half(tile[tx][r]);
}

// ---------------- tiled FIR with inline v-conv (writes P + Ph) ----------------
#define FIR_SMEM ((46 * 256 + 31 * 256 + 3 * 256) * 4)
__global__ __launch_bounds__(256) void fir_tiled_kernel(const float* __restrict__ vc,
                                                        const float* __restrict__ fs,
                                                        const float* __restrict__ fl) {
    float* vwin = (float*)dynsm;
    float* flm  = vwin + 46 * 256;
    float* fsm  = flm + 31 * 256;

    int t = threadIdx.x;
    int lt = blockIdx.x & 63;
    int bh = blockIdx.x >> 6;
    int h = bh & 3;
    int b = bh >> 2;
    int l0 = lt * 16;
    int ch = h * 256 + t;

    for (int idx = t; idx < 256 * 31; idx += 256) flm[idx] = fl[(size_t)h * 256 * 31 + idx];
    for (int idx = t; idx < 256 * 3; idx += 256)  fsm[idx] = fs[(size_t)h * 256 * 3 + idx];

    // inline v = silu(conv(qkvlin_v)) into vwin
    float4 vcw = *(const float4*)(vc + ch * 4);
    const float* vbase = g_qkvlin + 2048 + ch;
    for (int r = 0; r < 46; r++) {
        int l = l0 - 30 + r;
        float a = 0.f;
        if (l >= 0) {
#pragma unroll
            for (int j = 0; j < 4; j++) {
                int ls = l - 3 + j;
                if (ls >= 0) a += vbase[(size_t)(b * Ll + ls) * 3072] * f4c(vcw, j);
            }
            a = silu(a);
        }
        vwin[r * 256 + t] = a;
    }
    __syncthreads();

    const float* myfl = &flm[t * 31];
    const float* myfs = &fsm[t * 3];
    for (int li = 0; li < 16; li++) {
        float accL = 0.f;
#pragma unroll
        for (int j = 0; j < 31; j++) accL += vwin[(li + j) * 256 + t] * myfl[j];
        float accS = vwin[(li + 28) * 256 + t] * myfs[0]
                   + vwin[(li + 29) * 256 + t] * myfs[1]
                   + vwin[(li + 30) * 256 + t] * myfs[2];
        float vcur = vwin[(li + 30) * 256 + t];
        size_t row = ((size_t)b * Ll + l0 + li) * NHh + h;
        g_P [(row * 4 + 0) * 256 + t] = accS;
        g_P [(row * 4 + 1) * 256 + t] = accL;
        g_P [(row * 4 + 3) * 256 + t] = vcur;
        g_Ph[(row * 4 + 0) * 256 + t] = __float2half(accS);
        g_Ph[(row * 4 + 1) * 256 + t] = __float2half(accL);
        g_Ph[(row * 4 + 3) * 256 + t] = __float2half(vcur);
    }
}

// ---------------- delta pre (inline conv from qkvlin; float4 + register-tiled) ----------------
#define PADP 260
#define PRE_SMEM ((3 * 32 * PADP + 1024 + 1056 + 96) * 4)   // 108544 B

__global__ __launch_bounds__(256) void delta_pre_kernel(const float* __restrict__ qc,
                                                        const float* __restrict__ kc,
                                                        const float* __restrict__ vc) {
    float* smf = (float*)dynsm;
    float* qs  = smf;
    float* kn  = qs + 32 * PADP;
    float* vb  = kn + 32 * PADP;
    float* Am  = vb + 32 * PADP;
    float* Tm  = Am + 1024;
    float* bet = Tm + 1056;
    float* rsq = bet + 32;
    float* rsk = rsq + 32;

    int t  = threadIdx.x;
    int n  = blockIdx.x & 31;
    int bh = blockIdx.x >> 5;
    int h  = bh & 3;
    int b  = bh >> 2;
    int l0 = n * CHh;
    size_t obase = ((((size_t)b * NHh + h) * NCc + n) * CHh) * 256;

    // inline conv+silu staging from qkvlin
    {
        int d = (t & 63) << 2;            // fixed per thread
        int c4 = t >> 6;                  // 0..3
        int chq = h * 256 + d;
        float4 wq[4], wk[4], wv[4];
#pragma unroll
        for (int i = 0; i < 4; i++) {
            wq[i] = *(const float4*)(qc + (size_t)(chq + i) * 4);
            wk[i] = *(const float4*)(kc + (size_t)(chq + i) * 4);
            wv[i] = *(const float4*)(vc + (size_t)(chq + i) * 4);
        }
#pragma unroll
        for (int k8 = 0; k8 < 8; k8++) {
            int c = c4 + 4 * k8;
            int l = l0 + c;
            float4 aq = make_float4(0.f, 0.f, 0.f, 0.f);
            float4 ak = aq, av = aq;
#pragma unroll
            for (int j = 0; j < 4; j++) {
                int ls = l - 3 + j;
                if (ls >= 0) {
                    const float* rowp = g_qkvlin + (size_t)(b * Ll + ls) * 3072 + chq;
                    float4 xq = *(const float4*)(rowp);
                    float4 xk = *(const float4*)(rowp + 1024);
                    float4 xv = *(const float4*)(rowp + 2048);
                    aq.x += xq.x * f4c(wq[0], j); aq.y += xq.y * f4c(wq[1], j);
                    aq.z += xq.z * f4c(wq[2], j); aq.w += xq.w * f4c(wq[3], j);
                    ak.x += xk.x * f4c(wk[0], j); ak.y += xk.y * f4c(wk[1], j);
                    ak.z += xk.z * f4c(wk[2], j); ak.w += xk.w * f4c(wk[3], j);
                    av.x += xv.x * f4c(wv[0], j); av.y += xv.y * f4c(wv[1], j);
                    av.z += xv.z * f4c(wv[2], j); av.w += xv.w * f4c(wv[3], j);
                }
            }
            aq.x = silu(aq.x); aq.y = silu(aq.y); aq.z = silu(aq.z); aq.w = silu(aq.w);
            ak.x = silu(ak.x); ak.y = silu(ak.y); ak.z = silu(ak.z); ak.w = silu(ak.w);
            av.x = silu(av.x); av.y = silu(av.y); av.z = silu(av.z); av.w = silu(av.w);
            *(float4*)(&qs[c * PADP + d]) = aq;
            *(float4*)(&kn[c * PADP + d]) = ak;
            *(float4*)(&vb[c * PADP + d]) = av;
        }
    }
    if (t < CHh) bet[t] = g_beta[((size_t)b * Ll + l0 + t) * NHh + h];
    __syncthreads();

    int lane = t & 31;
    int wid = t >> 5;
    for (int r = wid; r < CHh; r += 8) {
        float sq = 0.f, sk = 0.f;
        for (int d = lane; d < 256; d += 32) {
            float a = qs[r * PADP + d]; sq += a * a;
            float c2 = kn[r * PADP + d]; sk += c2 * c2;
        }
        for (int o = 16; o; o >>= 1) {
            sq += __shfl_xor_sync(0xffffffffu, sq, o);
            sk += __shfl_xor_sync(0xffffffffu, sk, o);
        }
        if (!lane) { rsq[r] = rsqrtf(sq + 1e-6f); rsk[r] = rsqrtf(sk + 1e-6f); }
    }
    __syncthreads();

    for (int idx = t; idx < 32 * 64; idx += 256) {
        int c = idx >> 6;
        int d = (idx & 63) << 2;
        float4 qv = *(float4*)(&qs[c * PADP + d]);
        float4 kv = *(float4*)(&kn[c * PADP + d]);
        float4 vv = *(float4*)(&vb[c * PADP + d]);
        float rq = rsq[c], rk = rsk[c], bb2 = bet[c];
        qv.x *= rq; qv.y *= rq; qv.z *= rq; qv.w *= rq;
        kv.x *= rk; kv.y *= rk; kv.z *= rk; kv.w *= rk;
        vv.x *= bb2; vv.y *= bb2; vv.z *= bb2; vv.w *= bb2;
        *(float4*)(&qs[c * PADP + d]) = qv;
        *(float4*)(&kn[c * PADP + d]) = kv;
        *(float4*)(&vb[c * PADP + d]) = vv;
        *(float4*)(&g_qn[obase + c * 256 + d]) = qv;
        *(float4*)(&g_kn[obase + c * 256 + d]) = kv;
    }
    __syncthreads();

    // attn/A: 2x2 register-tiled float4 dot products
    {
        int ti = t >> 4;
        int tj = t & 15;
        const float* qA = &qs[ti * PADP];
        const float* qB = &qs[(ti + 16) * PADP];
        const float* kI0 = &kn[ti * PADP];
        const float* kI1 = &kn[(ti + 16) * PADP];
        const float* kJ0 = &kn[tj * PADP];
        const float* kJ1 = &kn[(tj + 16) * PADP];
        float dq00 = 0.f, dq01 = 0.f, dq10 = 0.f, dq11 = 0.f;
        float dk00 = 0.f, dk01 = 0.f, dk10 = 0.f, dk11 = 0.f;
#pragma unroll 4
        for (int d4 = 0; d4 < 64; d4++) {
            int d = d4 << 2;
            float4 a0 = *(const float4*)(&qA[d]);
            float4 a1 = *(const float4*)(&qB[d]);
            float4 b0 = *(const float4*)(&kJ0[d]);
            float4 b1 = *(const float4*)(&kJ1[d]);
            float4 c0 = *(const float4*)(&kI0[d]);
            float4 c1 = *(const float4*)(&kI1[d]);
            dq00 += a0.x * b0.x; dq00 += a0.y * b0.y; dq00 += a0.z * b0.z; dq00 += a0.w * b0.w;
            dq01 += a0.x * b1.x; dq01 += a0.y * b1.y; dq01 += a0.z * b1.z; dq01 += a0.w * b1.w;
            dq10 += a1.x * b0.x; dq10 += a1.y * b0.y; dq10 += a1.z * b0.z; dq10 += a1.w * b0.w;
            dq11 += a1.x * b1.x; dq11 += a1.y * b1.y; dq11 += a1.z * b1.z; dq11 += a1.w * b1.w;
            dk00 += c0.x * b0.x; dk00 += c0.y * b0.y; dk00 += c0.z * b0.z; dk00 += c0.w * b0.w;
            dk01 += c0.x * b1.x; dk01 += c0.y * b1.y; dk01 += c0.z * b1.z; dk01 += c0.w * b1.w;
            dk10 += c1.x * b0.x; dk10 += c1.y * b0.y; dk10 += c1.z * b0.z; dk10 += c1.w * b0.w;
            dk11 += c1.x * b1.x; dk11 += c1.y * b1.y; dk11 += c1.z * b1.z; dk11 += c1.w * b1.w;
        }
        size_t abase = ((((size_t)b * NHh + h) * NCc + n) << 10);
        int i0 = ti, i1 = ti + 16, j0 = tj, j1 = tj + 16;
        float bi0 = bet[i0], bi1 = bet[i1];
        Am[i0 * 32 + j0] = (j0 < i0) ? (-bi0 * dk00) : 0.f;
        Am[i0 * 32 + j1] = (j1 < i0) ? (-bi0 * dk01) : 0.f;
        Am[i1 * 32 + j0] = (j0 < i1) ? (-bi1 * dk10) : 0.f;
        Am[i1 * 32 + j1] = (j1 < i1) ? (-bi1 * dk11) : 0.f;
        g_attn[abase + i0 * 32 + j0] = (j0 <= i0) ? dq00 : 0.f;
        g_attn[abase + i0 * 32 + j1] = (j1 <= i0) ? dq01 : 0.f;
        g_attn[abase + i1 * 32 + j0] = (j0 <= i1) ? dq10 : 0.f;
        g_attn[abase + i1 * 32 + j1] = (j1 <= i1) ? dq11 : 0.f;
    }
    __syncthreads();

    if (t < 32) {
        Tm[t] = (t == 0) ? 1.f : 0.f;
        for (int i = 1; i < 32; i++) {
            float acc = (i == t) ? 1.f : 0.f;
            for (int m = 0; m < i; m++) acc += Am[i * 32 + m] * Tm[m * 33 + t];
            Tm[i * 33 + t] = acc;
        }
    }
    __syncthreads();

    {
        int d = t;
        float vbr[32], knr[32];
#pragma unroll
        for (int m = 0; m < 32; m++) {
            vbr[m] = vb[m * PADP + d];
            knr[m] = kn[m * PADP + d] * bet[m];
        }
#pragma unroll
        for (int r = 0; r < 32; r++) {
            float au = 0.f, aw = 0.f;
#pragma unroll
            for (int m = 0; m < 32; m++) {
                if (m <= r) {
                    float tv = Tm[r * 33 + m];
                    au += tv * vbr[m];
                    aw += tv * knr[m];
                }
            }
            g_u[obase + r * 256 + d] = au;
            g_w[obase + r * 256 + d] = aw;
        }
    }
}

// ---------------- serial chunk scan (writes P slot2 + Ph slot2) ----------------
#define KST 272
__global__ void scan_kernel() {
    float* smf = (float*)dynsm;
    float* S  = smf;
    float* qn = S + 4352;
    float* kn = qn + 8704;
    float* wS = kn + 8704;
    float* un = wS + 8704;
    float* uu = un + 544;
    float* at = uu + 512;

    int t = threadIdx.x;
    int s_idx = blockIdx.x & 15;
    int bh = blockIdx.x >> 4;
    int h = bh & 3;
    int b = bh >> 2;
    int j0 = s_idx * 16;

    for (int i = t; i < 4352; i += 256) S[i] = 0.f;
    __syncthreads();

    int j = t & 15;
    int cg = t >> 4;
    int c0 = cg * 2;
    int c1 = c0 + 1;

    for (int n = 0; n < NCc; n++) {
        size_t base = ((((size_t)b * NHh + h) * NCc + n) * CHh) * 256;
        for (int idx = t; idx < 32 * 64; idx += 256) {
            int c = idx >> 6;
            int dq = (idx & 63) << 2;
            *(float4*)(&qn[c * KST + dq]) = *(const float4*)(&g_qn[base + c * 256 + dq]);
            *(float4*)(&kn[c * KST + dq]) = *(const float4*)(&g_kn[base + c * 256 + dq]);
            *(float4*)(&wS[c * KST + dq]) = *(const float4*)(&g_w [base + c * 256 + dq]);
        }
        for (int idx = t; idx < 512; idx += 256) {
            int c = idx >> 4;
            int jj = idx & 15;
            uu[idx] = g_u[base + c * 256 + j0 + jj];
        }
        size_t abase = ((((size_t)b * NHh + h) * NCc + n) << 10);
        for (int idx = t; idx < 1024; idx += 256) {
            int c = idx >> 5;
            int cp = idx & 31;
            at[c * 33 + cp] = g_attn[abase + idx];
        }
        __syncthreads();

        float a0 = uu[c0 * 16 + j];
        float a1 = uu[c1 * 16 + j];
        float o0 = 0.f, o1 = 0.f;
        const float* w0 = &wS[c0 * KST];
        const float* w1 = &wS[c1 * KST];
        const float* q0 = &qn[c0 * KST];
        const float* q1 = &qn[c1 * KST];
#pragma unroll 8
        for (int d4 = 0; d4 < 64; d4++) {
            int d = d4 << 2;
            float4 wv0 = *(const float4*)(&w0[d]);
            float4 wv1 = *(const float4*)(&w1[d]);
            float4 qv0 = *(const float4*)(&q0[d]);
            float4 qv1 = *(const float4*)(&q1[d]);
            float s0 = S[(d + 0) * 17 + j];
            float s1 = S[(d + 1) * 17 + j];
            float s2 = S[(d + 2) * 17 + j];
            float s3 = S[(d + 3) * 17 + j];
            a0 -= wv0.x * s0 + wv0.y * s1 + wv0.z * s2 + wv0.w * s3;
            a1 -= wv1.x * s0 + wv1.y * s1 + wv1.z * s2 + wv1.w * s3;
            o0 += qv0.x * s0 + qv0.y * s1 + qv0.z * s2 + qv0.w * s3;
            o1 += qv1.x * s0 + qv1.y * s1 + qv1.z * s2 + qv1.w * s3;
        }
        un[c0 * 17 + j] = a0;
        un[c1 * 17 + j] = a1;
        __syncthreads();

        for (int cp = 0; cp <= c0; cp++) o0 += at[c0 * 33 + cp] * un[cp * 17 + j];
        for (int cp = 0; cp <= c1; cp++) o1 += at[c1 * 33 + cp] * un[cp * 17 + j];
        {
            int l = n * CHh;
            size_t r0 = (((size_t)b * Ll + l + c0) * NHh + h) * 4 + 2;
            size_t r1 = (((size_t)b * Ll + l + c1) * NHh + h) * 4 + 2;
            g_P [r0 * 256 + j0 + j] = o0;
            g_P [r1 * 256 + j0 + j] = o1;
            g_Ph[r0 * 256 + j0 + j] = __float2half(o0);
            g_Ph[r1 * 256 + j0 + j] = __float2half(o1);
        }

#pragma unroll
        for (int blk = 0; blk < 4; blk++) {
            int d0 = cg * 16 + blk * 4;
            float s0 = S[(d0 + 0) * 17 + j];
            float s1 = S[(d0 + 1) * 17 + j];
            float s2 = S[(d0 + 2) * 17 + j];
            float s3 = S[(d0 + 3) * 17 + j];
            for (int c = 0; c < 32; c++) {
                float u = un[c * 17 + j];
                float4 kv = *(const float4*)(&kn[c * KST + d0]);
                s0 += kv.x * u; s1 += kv.y * u; s2 += kv.z * u; s3 += kv.w * u;
            }
            S[(d0 + 0) * 17 + j] = s0;
            S[(d0 + 1) * 17 + j] = s1;
            S[(d0 + 2) * 17 + j] = s2;
            S[(d0 + 3) * 17 + j] = s3;
        }
        __syncthreads();
    }
}

// ---------------- gW1 stat-block column sums ----------------
__global__ void ssum_kernel(const float* __restrict__ gW1) {
    int idx = blockIdx.x * 256 + threadIdx.x;
    int s12 = idx / GHh;
    int nn = idx % GHh;
    float a = 0.f;
    const float* base = gW1 + (size_t)(1024 + s12 * 256) * GHh + nn;
    for (int r = 0; r < 256; r++) a += base[(size_t)r * GHh];
    g_ssum[idx] = a;
}

// ---------------- gate finalize (fused stats; P cached in smem; writes oh) ----------------
__global__ void gate_final_kernel(const float* __restrict__ gb1,
                                  const float* __restrict__ gW2,
                                  const float* __restrict__ gb2,
                                  const float* __restrict__ temp,
                                  const float* __restrict__ epsf,
                                  const float* __restrict__ onw) {
    __shared__ float mid[GHh];
    __shared__ float st[12];
    __shared__ float w4[4];
    __shared__ float red[256];
    __shared__ float rS[256], rQ[256], rM[256];
    __shared__ float Psm[1024];
    int row = blockIdx.x;
    int t = threadIdx.x;
    int h = row & 3;
    int bl = row >> 2;

    {
        int jb = t >> 6;
        int s = t & 63;
        const float* p = &g_P[((size_t)row * 4 + jb) << 8];
        float sm = 0.f, sq = 0.f, mx = -3.4e38f;
#pragma unroll
        for (int k = 0; k < 4; k++) {
            float v = p[s + 64 * k];
            Psm[jb * 256 + s + 64 * k] = v;
            sm += v; sq += v * v; mx = fmaxf(mx, v);
        }
        rS[t] = sm; rQ[t] = sq; rM[t] = mx;
        __syncthreads();
        for (int str = 32; str >= 1; str >>= 1) {
            if (s < str) {
                rS[t] += rS[t + str];
                rQ[t] += rQ[t + str];
                rM[t] = fmaxf(rM[t], rM[t + str]);
            }
            __syncthreads();
        }
        if (s == 0) {
            st[jb * 3 + 0] = rS[t] * (1.f / 256.f);
            st[jb * 3 + 1] = sqrtf(fmaxf(rQ[t] * (1.f / 256.f), 1e-8f));
            st[jb * 3 + 2] = rM[t];
        }
        __syncthreads();
    }

    for (int nn = t; nn < GHh; nn += 256) {
        float val = g_hid1[(size_t)bl * GHh + nn] + g_bpart[(size_t)row * GHh + nn] + gb1[nn];
#pragma unroll
        for (int s12 = 0; s12 < 12; s12++) val += st[s12] * g_ssum[s12 * GHh + nn];
        mid[nn] = 0.5f * val * (1.f + erff(val * 0.70710678118654752f));
    }
    __syncthreads();

    {
        int o = t & 3;
        float p = 0.f;
        for (int nidx = t >> 2; nidx < GHh; nidx += 64) p += mid[nidx] * gW2[nidx * 4 + o];
        red[t] = p;
    }
    __syncthreads();
    if (t < 4) {
        float lg = gb2[t];
        for (int g = 0; g < 64; g++) lg += red[g * 4 + t];
        red[t] = lg;
    }
    __syncthreads();
    if (t == 0) {
        float tc = fminf(fmaxf(temp[h], 0.2f), 10.f);
        float l0 = red[0] / tc, l1 = red[1] / tc, l2 = red[2] / tc, l3 = red[3] / tc;
        float mx = fmaxf(fmaxf(l0, l1), fmaxf(l2, l3));
        float e0 = expf(l0 - mx), e1 = expf(l1 - mx), e2 = expf(l2 - mx), e3 = expf(l3 - mx);
        float s = e0 + e1 + e2 + e3;
        float w0 = e0 / s, w1 = e1 / s, w2 = e2 / s, w3 = e3 / s;
        float f0 = fminf(fmaxf(epsf[h * 4 + 0], 1e-7f), 0.1f);
        float f1 = fminf(fmaxf(epsf[h * 4 + 1], 1e-7f), 0.1f);
        float f2 = fminf(fmaxf(epsf[h * 4 + 2], 1e-7f), 0.1f);
        float f3 = fminf(fmaxf(epsf[h * 4 + 3], 1e-7f), 0.1f);
        w0 = fmaxf(w0, f0); w1 = fmaxf(w1, f1); w2 = fmaxf(w2, f2); w3 = fmaxf(w3, f3);
        float s2 = w0 + w1 + w2 + w3;
        w4[0] = w0 / s2; w4[1] = w1 / s2; w4[2] = w2 / s2; w4[3] = w3 / s2;
    }
    __syncthreads();

    float od = 0.f;
#pragma unroll
    for (int jj = 0; jj < 4; jj++) od += w4[jj] * Psm[jj * 256 + t];
    red[t] = od * od;
    __syncthreads();
    for (int s = 128; s > 0; s >>= 1) {
        if (t < s) red[t] += red[t + s];
        __syncthreads();
    }
    float ms = red[0] * (1.f / 256.f);
    g_oh[(size_t)bl * HIDv + h * 256 + t] = __float2half(od * rsqrtf(ms + 1e-5f) * onw[t]);
}

// ---------------- host launcher ----------------
static const int SCAN_SMEM = 32576 * 4;

extern "C" void kernel_launch(void* const* d_in, const int* in_sizes, int n_in,
                              void* d_out, int out_size) {
    const float *x = 0, *Wq = 0, *Wk = 0, *Wv = 0, *Wb = 0, *qc = 0, *kc = 0, *vc = 0;
    const float *firs = 0, *firl = 0, *gW1 = 0, *gb1 = 0, *gW2 = 0, *gb2 = 0;
    const float *temp = 0, *epsf = 0, *onw = 0, *Wo = 0;
    int occ1M = 0, occ4k = 0, occ4 = 0;
    for (int i = 0; i < n_in; i++) {
        const float* p = (const float*)d_in[i];
        switch (in_sizes[i]) {
            case 2097152: x = p; break;
            case 1048576:
                if (occ1M == 0) Wq = p; else if (occ1M == 1) Wk = p;
                else if (occ1M == 2) Wv = p; else Wo = p;
                occ1M++; break;
            case 4096:
                if (occ4k == 0) Wb = p; else if (occ4k == 1) qc = p;
                else if (occ4k == 2) kc = p; else vc = p;
                occ4k++; break;
            case 2621440: gW1 = p; break;
            case 512:     gb1 = p; break;
            case 2048:    gW2 = p; break;
            case 4:       if (occ4 == 0) gb2 = p; else temp = p; occ4++; break;
            case 16:      epsf = p; break;
            case 256:     onw = p; break;
            case 3072:    firs = p; break;
            case 31744:   firl = p; break;
            default: break;
        }
    }

    float *p_qkvlin, *p_hid1, *p_bpart;
    cudaGetSymbolAddress((void**)&p_qkvlin, g_qkvlin);
    cudaGetSymbolAddress((void**)&p_hid1, g_hid1);
    cudaGetSymbolAddress((void**)&p_bpart, g_bpart);

    __half *xh, *Ph, *oh, *Wqkvh, *Woh, *g1ah, *g1bh;
    cudaGetSymbolAddress((void**)&xh, g_xh);
    cudaGetSymbolAddress((void**)&Ph, g_Ph);
    cudaGetSymbolAddress((void**)&oh, g_oh);
    cudaGetSymbolAddress((void**)&Wqkvh, g_Wqkvh);
    cudaGetSymbolAddress((void**)&Woh, g_Woh);
    cudaGetSymbolAddress((void**)&g1ah, g_g1ah);
    cudaGetSymbolAddress((void**)&g1bh, g_g1bh);

    cudaFuncSetAttribute(delta_pre_kernel, cudaFuncAttributeMaxDynamicSharedMemorySize, PRE_SMEM);
    cudaFuncSetAttribute(scan_kernel, cudaFuncAttributeMaxDynamicSharedMemorySize, SCAN_SMEM);
    cudaFuncSetAttribute(gemm_fp16, cudaFuncAttributeMaxDynamicSharedMemorySize, GEMM_SMEM);
    cudaFuncSetAttribute(fir_tiled_kernel, cudaFuncAttributeMaxDynamicSharedMemorySize, FIR_SMEM);

    const size_t W1M = (size_t)1024 * 1024;

    // single stream; launch #4 = merged QKV GEMM (profiled)
    beta_xh_kernel<<<256, 256>>>(x, Wb);                                          // 1
    htrans4_kernel<<<dim3(32, 32, 4), 256>>>(Wq, Wk, Wv, Wo,
        Wqkvh, Wqkvh + W1M, Wqkvh + 2 * W1M, Woh);                                // 2
    htrans2_kernel<<<dim3(16, 32, 2), 256>>>(gW1, gW1 + (size_t)4096 * 512,
                                             g1ah, g1bh, 1024, 512);              // 3
    gemm_fp16<<<dim3(12, 16), 256, GEMM_SMEM>>>(xh, Wqkvh, p_qkvlin, 2048, 3072, 1024);  // 4 <- profiled
    ssum_kernel<<<24, 256>>>(gW1);                                                // 5
    delta_pre_kernel<<<256, 256, PRE_SMEM>>>(qc, kc, vc);                         // 6
    scan_kernel<<<128, 256, SCAN_SMEM>>>();                                       // 7
    fir_tiled_kernel<<<512, 256, FIR_SMEM>>>(vc, firs, firl);                     // 8
    gemm_fp16<<<dim3(2, 16), 256, GEMM_SMEM>>>(xh, g1ah, p_hid1, 2048, 512, 1024);        // 9
    gemm_fp16<<<dim3(2, 64), 256, GEMM_SMEM>>>(Ph, g1bh, p_bpart, 8192, 512, 1024);       // 10
    gate_final_kernel<<<8192, 256>>>(gb1, gW2, gb2, temp, epsf, onw);             // 11
    gemm_fp16<<<dim3(4, 16), 256, GEMM_SMEM>>>(oh, Woh, (float*)d_out, 2048, 1024, 1024); // 12
}

// round 15
// speedup vs baseline: 1.0466x; 1.0466x over previous
#include <cuda_runtime.h>
#include <cuda_fp16.h>
#include <stdint.h>
#include <math.h>

// ---------------- problem constants ----------------
#define Bb   2
#define Ll   1024
#define HIDv 1024
#define NHh  4
#define DKk  256
#define NCc  32
#define CHh  32
#define BLr  2048
#define GHh  512

extern __shared__ char dynsm[];

// ---------------- scratch ----------------
__device__ float g_qkvlin[BLr * 3 * HIDv];
__device__ float g_v[BLr * HIDv];
__device__ float g_beta[BLr * NHh];
__device__ float g_qn[BLr * HIDv];
__device__ float g_kn[BLr * HIDv];
__device__ float g_u[BLr * HIDv];
__device__ float g_w[BLr * HIDv];
__device__ float g_attn[Bb * NHh * NCc * CHh * CHh];
__device__ float g_P[BLr * NHh * 4 * DKk];
__device__ float g_ssum[12 * GHh];
__device__ float g_hid1[BLr * GHh];
__device__ float g_bpart[BLr * NHh * GHh];

__device__ __half g_xh[BLr * HIDv];
__device__ __half g_Ph[BLr * NHh * 4 * DKk];
__device__ __half g_oh[BLr * HIDv];
__device__ __half g_Wqkvh[3 * HIDv * HIDv];
__device__ __half g_Woh[HIDv * HIDv];
__device__ __half g_g1ah[GHh * HIDv];
__device__ __half g_g1bh[GHh * HIDv];

// ---------------- PTX helpers ----------------
__device__ __forceinline__ uint32_t smem_u32(const void* p) {
    uint32_t a;
    asm("{ .reg .u64 t; cvta.to.shared.u64 t, %1; cvt.u32.u64 %0, t; }" : "=r"(a) : "l"(p));
    return a;
}
__device__ __forceinline__ void ldsm_x4(uint32_t* r, uint32_t addr) {
    asm volatile("ldmatrix.sync.aligned.m8n8.x4.shared.b16 {%0,%1,%2,%3}, [%4];"
                 : "=r"(r[0]), "=r"(r[1]), "=r"(r[2]), "=r"(r[3]) : "r"(addr));
}
__device__ __forceinline__ void mma16816h(float* d, const uint32_t* a, const uint32_t* b) {
    asm volatile(
        "mma.sync.aligned.m16n8k16.row.col.f32.f16.f16.f32 "
        "{%0,%1,%2,%3}, {%4,%5,%6,%7}, {%8,%9}, {%0,%1,%2,%3};"
        : "+f"(d[0]), "+f"(d[1]), "+f"(d[2]), "+f"(d[3])
        : "r"(a[0]), "r"(a[1]), "r"(a[2]), "r"(a[3]), "r"(b[0]), "r"(b[1]));
}
__device__ __forceinline__ float f4c(const float4& v, int j) {
    return j == 0 ? v.x : j == 1 ? v.y : j == 2 ? v.z : v.w;
}
__device__ __forceinline__ float silu(float z) {
    return z / (1.f + expf(-z));
}

// ---------------- single-term fp16 HMMA GEMM (R12-proven) ----------------
#define LDAh 40
#define TILEA (128 * LDAh * 2)
#define TILEBB (256 * LDAh * 2)
#define STAGEB (TILEA + TILEBB)
#define GEMM_SMEM (2 * STAGEB)

__global__ __launch_bounds__(256, 1) void gemm_fp16(
    const __half* __restrict__ A, const __half* __restrict__ B,
    float* __restrict__ C, int M, int N, int K) {
    char* smc = dynsm;
    uint32_t sbase = smem_u32(smc);
    int t = threadIdx.x;
    int lane = t & 31;
    int wid = t >> 5;
    int wm = wid & 1;
    int wn = wid >> 1;
    int m0 = blockIdx.y * 128;
    int n0 = blockIdx.x * 256;

    float acc[4][8][4];
#pragma unroll
    for (int i = 0; i < 4; i++)
#pragma unroll
        for (int j = 0; j < 8; j++)
#pragma unroll
            for (int c = 0; c < 4; c++) acc[i][j][c] = 0.f;

    uint4 rg[6];
    int ldrow = t >> 2;
    int ldq = t & 3;
    int soffA0 = ((ldrow)      * LDAh + ldq * 8) * 2;
    int soffA1 = ((ldrow + 64) * LDAh + ldq * 8) * 2;

    int a_off = ((wm * 64 + (lane & 15)) * LDAh + ((lane >> 4) << 3)) * 2;
    int b_off = ((wn * 64 + (lane & 7) + ((lane >> 4) << 3)) * LDAh + (((lane >> 3) & 1) << 3)) * 2;

    const int S = K / 32;

    {
        rg[0] = *(const uint4*)(A + (size_t)(m0 + ldrow) * K + ldq * 8);
        rg[1] = *(const uint4*)(A + (size_t)(m0 + ldrow + 64) * K + ldq * 8);
#pragma unroll
        for (int i = 0; i < 4; i++)
            rg[2 + i] = *(const uint4*)(B + (size_t)(n0 + ldrow + i * 64) * K + ldq * 8);
    }
    *(uint4*)(smc + soffA0) = rg[0];
    *(uint4*)(smc + soffA1) = rg[1];
#pragma unroll
    for (int i = 0; i < 4; i++)
        *(uint4*)(smc + TILEA + ((ldrow + i * 64) * LDAh + ldq * 8) * 2) = rg[2 + i];
    __syncthreads();

    for (int s = 0; s < S; s++) {
        int cur = s & 1;
        if (s + 1 < S) {
            int k0 = (s + 1) * 32;
            rg[0] = *(const uint4*)(A + (size_t)(m0 + ldrow) * K + k0 + ldq * 8);
            rg[1] = *(const uint4*)(A + (size_t)(m0 + ldrow + 64) * K + k0 + ldq * 8);
#pragma unroll
            for (int i = 0; i < 4; i++)
                rg[2 + i] = *(const uint4*)(B + (size_t)(n0 + ldrow + i * 64) * K + k0 + ldq * 8);
        }

        uint32_t sb = sbase + cur * STAGEB;
#pragma unroll
        for (int kk = 0; kk < 32; kk += 16) {
            uint32_t ah[4][4], bf[4][4];
#pragma unroll
            for (int mi = 0; mi < 4; mi++)
                ldsm_x4(ah[mi], sb + a_off + mi * 16 * LDAh * 2 + kk * 2);
#pragma unroll
            for (int nb = 0; nb < 4; nb++)
                ldsm_x4(bf[nb], sb + TILEA + b_off + nb * 16 * LDAh * 2 + kk * 2);
#pragma unroll
            for (int mi = 0; mi < 4; mi++)
#pragma unroll
                for (int nb = 0; nb < 4; nb++) {
                    mma16816h(acc[mi][nb * 2 + 0], ah[mi], &bf[nb][0]);
                    mma16816h(acc[mi][nb * 2 + 1], ah[mi], &bf[nb][2]);
                }
        }

        if (s + 1 < S) {
            char* bb = smc + ((s + 1) & 1) * STAGEB;
            *(uint4*)(bb + soffA0) = rg[0];
            *(uint4*)(bb + soffA1) = rg[1];
#pragma unroll
            for (int i = 0; i < 4; i++)
                *(uint4*)(bb + TILEA + ((ldrow + i * 64) * LDAh + ldq * 8) * 2) = rg[2 + i];
        }
        __syncthreads();
    }

    int frow = lane >> 2;
    int fcol = (lane & 3) * 2;
#pragma unroll
    for (int mi = 0; mi < 4; mi++) {
#pragma unroll
        for (int ni = 0; ni < 8; ni++) {
            int row = m0 + wm * 64 + mi * 16 + frow;
            int col = n0 + wn * 64 + ni * 8 + fcol;
            *(float2*)(C + (size_t)row * N + col) = make_float2(acc[mi][ni][0], acc[mi][ni][1]);
            *(float2*)(C + (size_t)(row + 8) * N + col) = make_float2(acc[mi][ni][2], acc[mi][ni][3]);
        }
    }
}

// ---------------- beta = sigmoid(x @ Wb) + x -> fp16 ----------------
__global__ void beta_xh_kernel(const float* __restrict__ x, const float* __restrict__ Wb) {
    int gw   = (blockIdx.x << 3) + (threadIdx.x >> 5);
    int lane = threadIdx.x & 31;
    const float* xr = x + (size_t)gw * HIDv;
    __half* xhr = g_xh + (size_t)gw * HIDv;
    float a0 = 0.f, a1 = 0.f, a2 = 0.f, a3 = 0.f;
    for (int r = lane; r < HIDv; r += 32) {
        float xv = xr[r];
        xhr[r] = __float2half(xv);
        const float* wb = Wb + r * 4;
        a0 += xv * wb[0]; a1 += xv * wb[1]; a2 += xv * wb[2]; a3 += xv * wb[3];
    }
    for (int o = 16; o; o >>= 1) {
        a0 += __shfl_xor_sync(0xffffffffu, a0, o);
        a1 += __shfl_xor_sync(0xffffffffu, a1, o);
        a2 += __shfl_xor_sync(0xffffffffu, a2, o);
        a3 += __shfl_xor_sync(0xffffffffu, a3, o);
    }
    if (!lane) {
        float* bp = &g_beta[gw * 4];
        bp[0] = 1.f / (1.f + expf(-a0));
        bp[1] = 1.f / (1.f + expf(-a1));
        bp[2] = 1.f / (1.f + expf(-a2));
        bp[3] = 1.f / (1.f + expf(-a3));
    }
}

// src [K][N] fp32 -> dst [N][K] fp16; 2-way z select
__global__ void htrans2_kernel(const float* __restrict__ s0, const float* __restrict__ s1,
                               __half* __restrict__ h0, __half* __restrict__ h1,
                               int K, int N) {
    __shared__ float tile[32][33];
    int z = blockIdx.z;
    const float* src = z ? s1 : s0;
    __half* hi = z ? h1 : h0;
    int k0 = blockIdx.y * 32;
    int n0 = blockIdx.x * 32;
    int tx = threadIdx.x & 31;
    int ty = threadIdx.x >> 5;
    for (int r = ty; r < 32; r += 8) tile[r][tx] = src[(size_t)(k0 + r) * N + n0 + tx];
    __syncthreads();
    for (int r = ty; r < 32; r += 8)
        hi[(size_t)(n0 + r) * K + k0 + tx] = __float2half(tile[tx][r]);
}

// 4 fused 1024x1024 weight transposes
__global__ void htrans4_kernel(const float* __restrict__ s0, const float* __restrict__ s1,
                               const float* __restrict__ s2, const float* __restrict__ s3,
                               __half* __restrict__ h0, __half* __restrict__ h1,
                               __half* __restrict__ h2, __half* __restrict__ h3) {
    __shared__ float tile[32][33];
    int z = blockIdx.z;
    const float* src = (z == 0) ? s0 : (z == 1) ? s1 : (z == 2) ? s2 : s3;
    __half* hi = (z == 0) ? h0 : (z == 1) ? h1 : (z == 2) ? h2 : h3;
    int k0 = blockIdx.y * 32;
    int n0 = blockIdx.x * 32;
    int tx = threadIdx.x & 31;
    int ty = threadIdx.x >> 5;
    for (int r = ty; r < 32; r += 8) tile[r][tx] = src[(size_t)(k0 + r) * 1024 + n0 + tx];
    __syncthreads();
    for (int r = ty; r < 32; r += 8)
        hi[(size_t)(n0 + r) * 1024 + k0 + tx] = __float2half(tile[tx][r]);
}

// ---------------- tiled FIR reading precomputed v (writes P + Ph) ----------------
#define FIR_SMEM ((46 * 256 + 31 * 256 + 3 * 256) * 4)
__global__ __launch_bounds__(256) void fir_tiled_kernel(const float* __restrict__ fs,
                                                        const float* __restrict__ fl) {
    float* vwin = (float*)dynsm;
    float* flm  = vwin + 46 * 256;
    float* fsm  = flm + 31 * 256;

    int t = threadIdx.x;
    int lt = blockIdx.x & 63;
    int bh = blockIdx.x >> 6;
    int h = bh & 3;
    int b = bh >> 2;
    int l0 = lt * 16;

    for (int idx = t; idx < 256 * 31; idx += 256) flm[idx] = fl[(size_t)h * 256 * 31 + idx];
    for (int idx = t; idx < 256 * 3; idx += 256)  fsm[idx] = fs[(size_t)h * 256 * 3 + idx];
    for (int r = 0; r < 46; r++) {
        int l = l0 - 30 + r;
        vwin[r * 256 + t] = (l >= 0) ? g_v[(((size_t)b * Ll + l) * NHh + h) * 256 + t] : 0.f;
    }
    __syncthreads();

    const float* myfl = &flm[t * 31];
    const float* myfs = &fsm[t * 3];
    for (int li = 0; li < 16; li++) {
        float accL = 0.f;
#pragma unroll
        for (int j = 0; j < 31; j++) accL += vwin[(li + j) * 256 + t] * myfl[j];
        float accS = vwin[(li + 28) * 256 + t] * myfs[0]
                   + vwin[(li + 29) * 256 + t] * myfs[1]
                   + vwin[(li + 30) * 256 + t] * myfs[2];
        float vcur = vwin[(li + 30) * 256 + t];
        size_t row = ((size_t)b * Ll + l0 + li) * NHh + h;
        g_P [(row * 4 + 0) * 256 + t] = accS;
        g_P [(row * 4 + 1) * 256 + t] = accL;
        g_P [(row * 4 + 3) * 256 + t] = vcur;
        g_Ph[(row * 4 + 0) * 256 + t] = __float2half(accS);
        g_Ph[(row * 4 + 1) * 256 + t] = __float2half(accL);
        g_Ph[(row * 4 + 3) * 256 + t] = __float2half(vcur);
    }
}

// ---------------- delta pre (inline conv; emits v; float4 + register-tiled) ----------------
#define PADP 260
#define PRE_SMEM ((3 * 32 * PADP + 1024 + 1056 + 96) * 4)   // 108544 B

__global__ __launch_bounds__(256) void delta_pre_kernel(const float* __restrict__ qc,
                                                        const float* __restrict__ kc,
                                                        const float* __restrict__ vc) {
    float* smf = (float*)dynsm;
    float* qs  = smf;
    float* kn  = qs + 32 * PADP;
    float* vb  = kn + 32 * PADP;
    float* Am  = vb + 32 * PADP;
    float* Tm  = Am + 1024;
    float* bet = Tm + 1056;
    float* rsq = bet + 32;
    float* rsk = rsq + 32;

    int t  = threadIdx.x;
    int n  = blockIdx.x & 31;
    int bh = blockIdx.x >> 5;
    int h  = bh & 3;
    int b  = bh >> 2;
    int l0 = n * CHh;
    size_t obase = ((((size_t)b * NHh + h) * NCc + n) * CHh) * 256;

    // inline conv+silu staging from qkvlin; also emit v for FIR
    {
        int d = (t & 63) << 2;
        int c4 = t >> 6;
        int chq = h * 256 + d;
        float4 wq[4], wk[4], wv[4];
#pragma unroll
        for (int i = 0; i < 4; i++) {
            wq[i] = *(const float4*)(qc + (size_t)(chq + i) * 4);
            wk[i] = *(const float4*)(kc + (size_t)(chq + i) * 4);
            wv[i] = *(const float4*)(vc + (size_t)(chq + i) * 4);
        }
#pragma unroll
        for (int k8 = 0; k8 < 8; k8++) {
            int c = c4 + 4 * k8;
            int l = l0 + c;
            float4 aq = make_float4(0.f, 0.f, 0.f, 0.f);
            float4 ak = aq, av = aq;
#pragma unroll
            for (int j = 0; j < 4; j++) {
                int ls = l - 3 + j;
                if (ls >= 0) {
                    const float* rowp = g_qkvlin + (size_t)(b * Ll + ls) * 3072 + chq;
                    float4 xq = *(const float4*)(rowp);
                    float4 xk = *(const float4*)(rowp + 1024);
                    float4 xv = *(const float4*)(rowp + 2048);
                    aq.x += xq.x * f4c(wq[0], j); aq.y += xq.y * f4c(wq[1], j);
                    aq.z += xq.z * f4c(wq[2], j); aq.w += xq.w * f4c(wq[3], j);
                    ak.x += xk.x * f4c(wk[0], j); ak.y += xk.y * f4c(wk[1], j);
                    ak.z += xk.z * f4c(wk[2], j); ak.w += xk.w * f4c(wk[3], j);
                    av.x += xv.x * f4c(wv[0], j); av.y += xv.y * f4c(wv[1], j);
                    av.z += xv.z * f4c(wv[2], j); av.w += xv.w * f4c(wv[3], j);
                }
            }
            aq.x = silu(aq.x); aq.y = silu(aq.y); aq.z = silu(aq.z); aq.w = silu(aq.w);
            ak.x = silu(ak.x); ak.y = silu(ak.y); ak.z = silu(ak.z); ak.w = silu(ak.w);
            av.x = silu(av.x); av.y = silu(av.y); av.z = silu(av.z); av.w = silu(av.w);
            *(float4*)(&qs[c * PADP + d]) = aq;
            *(float4*)(&kn[c * PADP + d]) = ak;
            *(float4*)(&vb[c * PADP + d]) = av;
            *(float4*)(&g_v[(((size_t)b * Ll + l) * NHh + h) * 256 + d]) = av;
        }
    }
    if (t < CHh) bet[t] = g_beta[((size_t)b * Ll + l0 + t) * NHh + h];
    __syncthreads();

    int lane = t & 31;
    int wid = t >> 5;
    for (int r = wid; r < CHh; r += 8) {
        float sq = 0.f, sk = 0.f;
        for (int d = lane; d < 256; d += 32) {
            float a = qs[r * PADP + d]; sq += a * a;
            float c2 = kn[r * PADP + d]; sk += c2 * c2;
        }
        for (int o = 16; o; o >>= 1) {
            sq += __shfl_xor_sync(0xffffffffu, sq, o);
            sk += __shfl_xor_sync(0xffffffffu, sk, o);
        }
        if (!lane) { rsq[r] = rsqrtf(sq + 1e-6f); rsk[r] = rsqrtf(sk + 1e-6f); }
    }
    __syncthreads();

    for (int idx = t; idx < 32 * 64; idx += 256) {
        int c = idx >> 6;
        int d = (idx & 63) << 2;
        float4 qv = *(float4*)(&qs[c * PADP + d]);
        float4 kv = *(float4*)(&kn[c * PADP + d]);
        float4 vv = *(float4*)(&vb[c * PADP + d]);
        float rq = rsq[c], rk = rsk[c], bb2 = bet[c];
        qv.x *= rq; qv.y *= rq; qv.z *= rq; qv.w *= rq;
        kv.x *= rk; kv.y *= rk; kv.z *= rk; kv.w *= rk;
        vv.x *= bb2; vv.y *= bb2; vv.z *= bb2; vv.w *= bb2;
        *(float4*)(&qs[c * PADP + d]) = qv;
        *(float4*)(&kn[c * PADP + d]) = kv;
        *(float4*)(&vb[c * PADP + d]) = vv;
        *(float4*)(&g_qn[obase + c * 256 + d]) = qv;
        *(float4*)(&g_kn[obase + c * 256 + d]) = kv;
    }
    __syncthreads();

    // attn/A: 2x2 register-tiled float4 dot products
    {
        int ti = t >> 4;
        int tj = t & 15;
        const float* qA = &qs[ti * PADP];
        const float* qB = &qs[(ti + 16) * PADP];
        const float* kI0 = &kn[ti * PADP];
        const float* kI1 = &kn[(ti + 16) * PADP];
        const float* kJ0 = &kn[tj * PADP];
        const float* kJ1 = &kn[(tj + 16) * PADP];
        float dq00 = 0.f, dq01 = 0.f, dq10 = 0.f, dq11 = 0.f;
        float dk00 = 0.f, dk01 = 0.f, dk10 = 0.f, dk11 = 0.f;
#pragma unroll 4
        for (int d4 = 0; d4 < 64; d4++) {
            int d = d4 << 2;
            float4 a0 = *(const float4*)(&qA[d]);
            float4 a1 = *(const float4*)(&qB[d]);
            float4 b0 = *(const float4*)(&kJ0[d]);
            float4 b1 = *(const float4*)(&kJ1[d]);
            float4 c0 = *(const float4*)(&kI0[d]);
            float4 c1 = *(const float4*)(&kI1[d]);
            dq00 += a0.x * b0.x; dq00 += a0.y * b0.y; dq00 += a0.z * b0.z; dq00 += a0.w * b0.w;
            dq01 += a0.x * b1.x; dq01 += a0.y * b1.y; dq01 += a0.z * b1.z; dq01 += a0.w * b1.w;
            dq10 += a1.x * b0.x; dq10 += a1.y * b0.y; dq10 += a1.z * b0.z; dq10 += a1.w * b0.w;
            dq11 += a1.x * b1.x; dq11 += a1.y * b1.y; dq11 += a1.z * b1.z; dq11 += a1.w * b1.w;
            dk00 += c0.x * b0.x; dk00 += c0.y * b0.y; dk00 += c0.z * b0.z; dk00 += c0.w * b0.w;
            dk01 += c0.x * b1.x; dk01 += c0.y * b1.y; dk01 += c0.z * b1.z; dk01 += c0.w * b1.w;
            dk10 += c1.x * b0.x; dk10 += c1.y * b0.y; dk10 += c1.z * b0.z; dk10 += c1.w * b0.w;
            dk11 += c1.x * b1.x; dk11 += c1.y * b1.y; dk11 += c1.z * b1.z; dk11 += c1.w * b1.w;
        }
        size_t abase = ((((size_t)b * NHh + h) * NCc + n) << 10);
        int i0 = ti, i1 = ti + 16, j0 = tj, j1 = tj + 16;
        float bi0 = bet[i0], bi1 = bet[i1];
        Am[i0 * 32 + j0] = (j0 < i0) ? (-bi0 * dk00) : 0.f;
        Am[i0 * 32 + j1] = (j1 < i0) ? (-bi0 * dk01) : 0.f;
        Am[i1 * 32 + j0] = (j0 < i1) ? (-bi1 * dk10) : 0.f;
        Am[i1 * 32 + j1] = (j1 < i1) ? (-bi1 * dk11) : 0.f;
        g_attn[abase + i0 * 32 + j0] = (j0 <= i0) ? dq00 : 0.f;
        g_attn[abase + i0 * 32 + j1] = (j1 <= i0) ? dq01 : 0.f;
        g_attn[abase + i1 * 32 + j0] = (j0 <= i1) ? dq10 : 0.f;
        g_attn[abase + i1 * 32 + j1] = (j1 <= i1) ? dq11 : 0.f;
    }
    __syncthreads();

    if (t < 32) {
        Tm[t] = (t == 0) ? 1.f : 0.f;
        for (int i = 1; i < 32; i++) {
            float acc = (i == t) ? 1.f : 0.f;
            for (int m = 0; m < i; m++) acc += Am[i * 32 + m] * Tm[m * 33 + t];
            Tm[i * 33 + t] = acc;
        }
    }
    __syncthreads();

    {
        int d = t;
        float vbr[32], knr[32];
#pragma unroll
        for (int m = 0; m < 32; m++) {
            vbr[m] = vb[m * PADP + d];
            knr[m] = kn[m * PADP + d] * bet[m];
        }
#pragma unroll
        for (int r = 0; r < 32; r++) {
            float au = 0.f, aw = 0.f;
#pragma unroll
            for (int m = 0; m < 32; m++) {
                if (m <= r) {
                    float tv = Tm[r * 33 + m];
                    au += tv * vbr[m];
                    aw += tv * knr[m];
                }
            }
            g_u[obase + r * 256 + d] = au;
            g_w[obase + r * 256 + d] = aw;
        }
    }
}

// ---------------- serial chunk scan (writes P slot2 + Ph slot2) ----------------
#define KST 272
__global__ void scan_kernel() {
    float* smf = (float*)dynsm;
    float* S  = smf;
    float* qn = S + 4352;
    float* kn = qn + 8704;
    float* wS = kn + 8704;
    float* un = wS + 8704;
    float* uu = un + 544;
    float* at = uu + 512;

    int t = threadIdx.x;
    int s_idx = blockIdx.x & 15;
    int bh = blockIdx.x >> 4;
    int h = bh & 3;
    int b = bh >> 2;
    int j0 = s_idx * 16;

    for (int i = t; i < 4352; i += 256) S[i] = 0.f;
    __syncthreads();

    int j = t & 15;
    int cg = t >> 4;
    int c0 = cg * 2;
    int c1 = c0 + 1;

    for (int n = 0; n < NCc; n++) {
        size_t base = ((((size_t)b * NHh + h) * NCc + n) * CHh) * 256;
        for (int idx = t; idx < 32 * 64; idx += 256) {
            int c = idx >> 6;
            int dq = (idx & 63) << 2;
            *(float4*)(&qn[c * KST + dq]) = *(const float4*)(&g_qn[base + c * 256 + dq]);
            *(float4*)(&kn[c * KST + dq]) = *(const float4*)(&g_kn[base + c * 256 + dq]);
            *(float4*)(&wS[c * KST + dq]) = *(const float4*)(&g_w [base + c * 256 + dq]);
        }
        for (int idx = t; idx < 512; idx += 256) {
            int c = idx >> 4;
            int jj = idx & 15;
            uu[idx] = g_u[base + c * 256 + j0 + jj];
        }
        size_t abase = ((((size_t)b * NHh + h) * NCc + n) << 10);
        for (int idx = t; idx < 1024; idx += 256) {
            int c = idx >> 5;
            int cp = idx & 31;
            at[c * 33 + cp] = g_attn[abase + idx];
        }
        __syncthreads();

        float a0 = uu[c0 * 16 + j];
        float a1 = uu[c1 * 16 + j];
        float o0 = 0.f, o1 = 0.f;
        const float* w0 = &wS[c0 * KST];
        const float* w1 = &wS[c1 * KST];
        const float* q0 = &qn[c0 * KST];
        const float* q1 = &qn[c1 * KST];
#pragma unroll 8
        for (int d4 = 0; d4 < 64; d4++) {
            int d = d4 << 2;
            float4 wv0 = *(const float4*)(&w0[d]);
            float4 wv1 = *(const float4*)(&w1[d]);
            float4 qv0 = *(const float4*)(&q0[d]);
            float4 qv1 = *(const float4*)(&q1[d]);
            float s0 = S[(d + 0) * 17 + j];
            float s1 = S[(d + 1) * 17 + j];
            float s2 = S[(d + 2) * 17 + j];
            float s3 = S[(d + 3) * 17 + j];
            a0 -= wv0.x * s0 + wv0.y * s1 + wv0.z * s2 + wv0.w * s3;
            a1 -= wv1.x * s0 + wv1.y * s1 + wv1.z * s2 + wv1.w * s3;
            o0 += qv0.x * s0 + qv0.y * s1 + qv0.z * s2 + qv0.w * s3;
            o1 += qv1.x * s0 + qv1.y * s1 + qv1.z * s2 + qv1.w * s3;
        }
        un[c0 * 17 + j] = a0;
        un[c1 * 17 + j] = a1;
        __syncthreads();

        for (int cp = 0; cp <= c0; cp++) o0 += at[c0 * 33 + cp] * un[cp * 17 + j];
        for (int cp = 0; cp <= c1; cp++) o1 += at[c1 * 33 + cp] * un[cp * 17 + j];
        {
            int l = n * CHh;
            size_t r0 = (((size_t)b * Ll + l + c0) * NHh + h) * 4 + 2;
            size_t r1 = (((size_t)b * Ll + l + c1) * NHh + h) * 4 + 2;
            g_P [r0 * 256 + j0 + j] = o0;
            g_P [r1 * 256 + j0 + j] = o1;
            g_Ph[r0 * 256 + j0 + j] = __float2half(o0);
            g_Ph[r1 * 256 + j0 + j] = __float2half(o1);
        }

#pragma unroll
        for (int blk = 0; blk < 4; blk++) {
            int d0 = cg * 16 + blk * 4;
            float s0 = S[(d0 + 0) * 17 + j];
            float s1 = S[(d0 + 1) * 17 + j];
            float s2 = S[(d0 + 2) * 17 + j];
            float s3 = S[(d0 + 3) * 17 + j];
            for (int c = 0; c < 32; c++) {
                float u = un[c * 17 + j];
                float4 kv = *(const float4*)(&kn[c * KST + d0]);
                s0 += kv.x * u; s1 += kv.y * u; s2 += kv.z * u; s3 += kv.w * u;
            }
            S[(d0 + 0) * 17 + j] = s0;
            S[(d0 + 1) * 17 + j] = s1;
            S[(d0 + 2) * 17 + j] = s2;
            S[(d0 + 3) * 17 + j] = s3;
        }
        __syncthreads();
    }
}

// ---------------- gW1 stat-block column sums ----------------
__global__ void ssum_kernel(const float* __restrict__ gW1) {
    int idx = blockIdx.x * 256 + threadIdx.x;
    int s12 = idx / GHh;
    int nn = idx % GHh;
    float a = 0.f;
    const float* base = gW1 + (size_t)(1024 + s12 * 256) * GHh + nn;
    for (int r = 0; r < 256; r++) a += base[(size_t)r * GHh];
    g_ssum[idx] = a;
}

// ---------------- gate finalize (fused stats; P cached in smem; writes oh) ----------------
__global__ void gate_final_kernel(const float* __restrict__ gb1,
                                  const float* __restrict__ gW2,
                                  const float* __restrict__ gb2,
                                  const float* __restrict__ temp,
                                  const float* __restrict__ epsf,
                                  const float* __restrict__ onw) {
    __shared__ float mid[GHh];
    __shared__ float st[12];
    __shared__ float w4[4];
    __shared__ float red[256];
    __shared__ float rS[256], rQ[256], rM[256];
    __shared__ float Psm[1024];
    int row = blockIdx.x;
    int t = threadIdx.x;
    int h = row & 3;
    int bl = row >> 2;

    {
        int jb = t >> 6;
        int s = t & 63;
        const float* p = &g_P[((size_t)row * 4 + jb) << 8];
        float sm = 0.f, sq = 0.f, mx = -3.4e38f;
#pragma unroll
        for (int k = 0; k < 4; k++) {
            float v = p[s + 64 * k];
            Psm[jb * 256 + s + 64 * k] = v;
            sm += v; sq += v * v; mx = fmaxf(mx, v);
        }
        rS[t] = sm; rQ[t] = sq; rM[t] = mx;
        __syncthreads();
        for (int str = 32; str >= 1; str >>= 1) {
            if (s < str) {
                rS[t] += rS[t + str];
                rQ[t] += rQ[t + str];
                rM[t] = fmaxf(rM[t], rM[t + str]);
            }
            __syncthreads();
        }
        if (s == 0) {
            st[jb * 3 + 0] = rS[t] * (1.f / 256.f);
            st[jb * 3 + 1] = sqrtf(fmaxf(rQ[t] * (1.f / 256.f), 1e-8f));
            st[jb * 3 + 2] = rM[t];
        }
        __syncthreads();
    }

    for (int nn = t; nn < GHh; nn += 256) {
        float val = g_hid1[(size_t)bl * GHh + nn] + g_bpart[(size_t)row * GHh + nn] + gb1[nn];
#pragma unroll
        for (int s12 = 0; s12 < 12; s12++) val += st[s12] * g_ssum[s12 * GHh + nn];
        mid[nn] = 0.5f * val * (1.f + erff(val * 0.70710678118654752f));
    }
    __syncthreads();

    {
        int o = t & 3;
        float p = 0.f;
        for (int nidx = t >> 2; nidx < GHh; nidx += 64) p += mid[nidx] * gW2[nidx * 4 + o];
        red[t] = p;
    }
    __syncthreads();
    if (t < 4) {
        float lg = gb2[t];
        for (int g = 0; g < 64; g++) lg += red[g * 4 + t];
        red[t] = lg;
    }
    __syncthreads();
    if (t == 0) {
        float tc = fminf(fmaxf(temp[h], 0.2f), 10.f);
        float l0 = red[0] / tc, l1 = red[1] / tc, l2 = red[2] / tc, l3 = red[3] / tc;
        float mx = fmaxf(fmaxf(l0, l1), fmaxf(l2, l3));
        float e0 = expf(l0 - mx), e1 = expf(l1 - mx), e2 = expf(l2 - mx), e3 = expf(l3 - mx);
        float s = e0 + e1 + e2 + e3;
        float w0 = e0 / s, w1 = e1 / s, w2 = e2 / s, w3 = e3 / s;
        float f0 = fminf(fmaxf(epsf[h * 4 + 0], 1e-7f), 0.1f);
        float f1 = fminf(fmaxf(epsf[h * 4 + 1], 1e-7f), 0.1f);
        float f2 = fminf(fmaxf(epsf[h * 4 + 2], 1e-7f), 0.1f);
        float f3 = fminf(fmaxf(epsf[h * 4 + 3], 1e-7f), 0.1f);
        w0 = fmaxf(w0, f0); w1 = fmaxf(w1, f1); w2 = fmaxf(w2, f2); w3 = fmaxf(w3, f3);
        float s2 = w0 + w1 + w2 + w3;
        w4[0] = w0 / s2; w4[1] = w1 / s2; w4[2] = w2 / s2; w4[3] = w3 / s2;
    }
    __syncthreads();

    float od = 0.f;
#pragma unroll
    for (int jj = 0; jj < 4; jj++) od += w4[jj] * Psm[jj * 256 + t];
    red[t] = od * od;
    __syncthreads();
    for (int s = 128; s > 0; s >>= 1) {
        if (t < s) red[t] += red[t + s];
        __syncthreads();
    }
    float ms = red[0] * (1.f / 256.f);
    g_oh[(size_t)bl * HIDv + h * 256 + t] = __float2half(od * rsqrtf(ms + 1e-5f) * onw[t]);
}

// ---------------- host launcher ----------------
static const int SCAN_SMEM = 32576 * 4;

extern "C" void kernel_launch(void* const* d_in, const int* in_sizes, int n_in,
                              void* d_out, int out_size) {
    const float *x = 0, *Wq = 0, *Wk = 0, *Wv = 0, *Wb = 0, *qc = 0, *kc = 0, *vc = 0;
    const float *firs = 0, *firl = 0, *gW1 = 0, *gb1 = 0, *gW2 = 0, *gb2 = 0;
    const float *temp = 0, *epsf = 0, *onw = 0, *Wo = 0;
    int occ1M = 0, occ4k = 0, occ4 = 0;
    for (int i = 0; i < n_in; i++) {
        const float* p = (const float*)d_in[i];
        switch (in_sizes[i]) {
            case 2097152: x = p; break;
            case 1048576:
                if (occ1M == 0) Wq = p; else if (occ1M == 1) Wk = p;
                else if (occ1M == 2) Wv = p; else Wo = p;
                occ1M++; break;
            case 4096:
                if (occ4k == 0) Wb = p; else if (occ4k == 1) qc = p;
                else if (occ4k == 2) kc = p; else vc = p;
                occ4k++; break;
            case 2621440: gW1 = p; break;
            case 512:     gb1 = p; break;
            case 2048:    gW2 = p; break;
            case 4:       if (occ4 == 0) gb2 = p; else temp = p; occ4++; break;
            case 16:      epsf = p; break;
            case 256:     onw = p; break;
            case 3072:    firs = p; break;
            case 31744:   firl = p; break;
            default: break;
        }
    }

    float *p_qkvlin, *p_hid1, *p_bpart;
    cudaGetSymbolAddress((void**)&p_qkvlin, g_qkvlin);
    cudaGetSymbolAddress((void**)&p_hid1, g_hid1);
    cudaGetSymbolAddress((void**)&p_bpart, g_bpart);

    __half *xh, *Ph, *oh, *Wqkvh, *Woh, *g1ah, *g1bh;
    cudaGetSymbolAddress((void**)&xh, g_xh);
    cudaGetSymbolAddress((void**)&Ph, g_Ph);
    cudaGetSymbolAddress((void**)&oh, g_oh);
    cudaGetSymbolAddress((void**)&Wqkvh, g_Wqkvh);
    cudaGetSymbolAddress((void**)&Woh, g_Woh);
    cudaGetSymbolAddress((void**)&g1ah, g_g1ah);
    cudaGetSymbolAddress((void**)&g1bh, g_g1bh);

    cudaFuncSetAttribute(delta_pre_kernel, cudaFuncAttributeMaxDynamicSharedMemorySize, PRE_SMEM);
    cudaFuncSetAttribute(scan_kernel, cudaFuncAttributeMaxDynamicSharedMemorySize, SCAN_SMEM);
    cudaFuncSetAttribute(gemm_fp16, cudaFuncAttributeMaxDynamicSharedMemorySize, GEMM_SMEM);
    cudaFuncSetAttribute(fir_tiled_kernel, cudaFuncAttributeMaxDynamicSharedMemorySize, FIR_SMEM);

    const size_t W1M = (size_t)1024 * 1024;

    // single stream; launch #4 = merged QKV GEMM (profiled)
    beta_xh_kernel<<<256, 256>>>(x, Wb);                                          // 1
    htrans4_kernel<<<dim3(32, 32, 4), 256>>>(Wq, Wk, Wv, Wo,
        Wqkvh, Wqkvh + W1M, Wqkvh + 2 * W1M, Woh);                                // 2
    htrans2_kernel<<<dim3(16, 32, 2), 256>>>(gW1, gW1 + (size_t)4096 * 512,
                                             g1ah, g1bh, 1024, 512);              // 3
    gemm_fp16<<<dim3(12, 16), 256, GEMM_SMEM>>>(xh, Wqkvh, p_qkvlin, 2048, 3072, 1024);  // 4 <- profiled
    ssum_kernel<<<24, 256>>>(gW1);                                                // 5
    delta_pre_kernel<<<256, 256, PRE_SMEM>>>(qc, kc, vc);                         // 6
    scan_kernel<<<128, 256, SCAN_SMEM>>>();                                       // 7
    fir_tiled_kernel<<<512, 256, FIR_SMEM>>>(firs, firl);                         // 8
    gemm_fp16<<<dim3(2, 16), 256, GEMM_SMEM>>>(xh, g1ah, p_hid1, 2048, 512, 1024);        // 9
    gemm_fp16<<<dim3(2, 64), 256, GEMM_SMEM>>>(Ph, g1bh, p_bpart, 8192, 512, 1024);       // 10
    gate_final_kernel<<<8192, 256>>>(gb1, gW2, gb2, temp, epsf, onw);             // 11
    gemm_fp16<<<dim3(4, 16), 256, GEMM_SMEM>>>(oh, Woh, (float*)d_out, 2048, 1024, 1024); // 12
}

// round 16
// speedup vs baseline: 1.0834x; 1.0352x over previous
#include <cuda_runtime.h>
#include <cuda_fp16.h>
#include <stdint.h>
#include <math.h>

// ---------------- problem constants ----------------
#define Bb   2
#define Ll   1024
#define HIDv 1024
#define NHh  4
#define DKk  256
#define NCc  32
#define CHh  32
#define BLr  2048
#define GHh  512

extern __shared__ char dynsm[];

// ---------------- scratch ----------------
__device__ float g_qkvlin[BLr * 3 * HIDv];
__device__ float g_v[BLr * HIDv];
__device__ float g_beta[BLr * NHh];
__device__ float g_qn[BLr * HIDv];
__device__ float g_kn[BLr * HIDv];
__device__ float g_u[BLr * HIDv];
__device__ float g_w[BLr * HIDv];
__device__ float g_attn[Bb * NHh * NCc * CHh * CHh];
__device__ float g_P[BLr * NHh * 4 * DKk];
__device__ float g_ssum[12 * GHh];
__device__ float g_hid1[BLr * GHh];
__device__ float g_bpart[BLr * NHh * GHh];

__device__ __half g_xh[BLr * HIDv];
__device__ __half g_Ph[BLr * NHh * 4 * DKk];
__device__ __half g_oh[BLr * HIDv];
__device__ __half g_Wqkvh[3 * HIDv * HIDv];
__device__ __half g_Woh[HIDv * HIDv];
__device__ __half g_g1ah[GHh * HIDv];
__device__ __half g_g1bh[GHh * HIDv];

// ---------------- PTX helpers ----------------
__device__ __forceinline__ uint32_t smem_u32(const void* p) {
    uint32_t a;
    asm("{ .reg .u64 t; cvta.to.shared.u64 t, %1; cvt.u32.u64 %0, t; }" : "=r"(a) : "l"(p));
    return a;
}
__device__ __forceinline__ void ldsm_x4(uint32_t* r, uint32_t addr) {
    asm volatile("ldmatrix.sync.aligned.m8n8.x4.shared.b16 {%0,%1,%2,%3}, [%4];"
                 : "=r"(r[0]), "=r"(r[1]), "=r"(r[2]), "=r"(r[3]) : "r"(addr));
}
__device__ __forceinline__ void mma16816h(float* d, const uint32_t* a, const uint32_t* b) {
    asm volatile(
        "mma.sync.aligned.m16n8k16.row.col.f32.f16.f16.f32 "
        "{%0,%1,%2,%3}, {%4,%5,%6,%7}, {%8,%9}, {%0,%1,%2,%3};"
        : "+f"(d[0]), "+f"(d[1]), "+f"(d[2]), "+f"(d[3])
        : "r"(a[0]), "r"(a[1]), "r"(a[2]), "r"(a[3]), "r"(b[0]), "r"(b[1]));
}
__device__ __forceinline__ float f4c(const float4& v, int j) {
    return j == 0 ? v.x : j == 1 ? v.y : j == 2 ? v.z : v.w;
}
__device__ __forceinline__ float silu(float z) {
    return z / (1.f + expf(-z));
}

// ---------------- single-term fp16 HMMA GEMM (R12-proven) ----------------
#define LDAh 40
#define TILEA (128 * LDAh * 2)
#define TILEBB (256 * LDAh * 2)
#define STAGEB (TILEA + TILEBB)
#define GEMM_SMEM (2 * STAGEB)

__global__ __launch_bounds__(256, 1) void gemm_fp16(
    const __half* __restrict__ A, const __half* __restrict__ B,
    float* __restrict__ C, int M, int N, int K) {
    char* smc = dynsm;
    uint32_t sbase = smem_u32(smc);
    int t = threadIdx.x;
    int lane = t & 31;
    int wid = t >> 5;
    int wm = wid & 1;
    int wn = wid >> 1;
    int m0 = blockIdx.y * 128;
    int n0 = blockIdx.x * 256;

    float acc[4][8][4];
#pragma unroll
    for (int i = 0; i < 4; i++)
#pragma unroll
        for (int j = 0; j < 8; j++)
#pragma unroll
            for (int c = 0; c < 4; c++) acc[i][j][c] = 0.f;

    uint4 rg[6];
    int ldrow = t >> 2;
    int ldq = t & 3;
    int soffA0 = ((ldrow)      * LDAh + ldq * 8) * 2;
    int soffA1 = ((ldrow + 64) * LDAh + ldq * 8) * 2;

    int a_off = ((wm * 64 + (lane & 15)) * LDAh + ((lane >> 4) << 3)) * 2;
    int b_off = ((wn * 64 + (lane & 7) + ((lane >> 4) << 3)) * LDAh + (((lane >> 3) & 1) << 3)) * 2;

    const int S = K / 32;

    {
        rg[0] = *(const uint4*)(A + (size_t)(m0 + ldrow) * K + ldq * 8);
        rg[1] = *(const uint4*)(A + (size_t)(m0 + ldrow + 64) * K + ldq * 8);
#pragma unroll
        for (int i = 0; i < 4; i++)
            rg[2 + i] = *(const uint4*)(B + (size_t)(n0 + ldrow + i * 64) * K + ldq * 8);
    }
    *(uint4*)(smc + soffA0) = rg[0];
    *(uint4*)(smc + soffA1) = rg[1];
#pragma unroll
    for (int i = 0; i < 4; i++)
        *(uint4*)(smc + TILEA + ((ldrow + i * 64) * LDAh + ldq * 8) * 2) = rg[2 + i];
    __syncthreads();

    for (int s = 0; s < S; s++) {
        int cur = s & 1;
        if (s + 1 < S) {
            int k0 = (s + 1) * 32;
            rg[0] = *(const uint4*)(A + (size_t)(m0 + ldrow) * K + k0 + ldq * 8);
            rg[1] = *(const uint4*)(A + (size_t)(m0 + ldrow + 64) * K + k0 + ldq * 8);
#pragma unroll
            for (int i = 0; i < 4; i++)
                rg[2 + i] = *(const uint4*)(B + (size_t)(n0 + ldrow + i * 64) * K + k0 + ldq * 8);
        }

        uint32_t sb = sbase + cur * STAGEB;
#pragma unroll
        for (int kk = 0; kk < 32; kk += 16) {
            uint32_t ah[4][4], bf[4][4];
#pragma unroll
            for (int mi = 0; mi < 4; mi++)
                ldsm_x4(ah[mi], sb + a_off + mi * 16 * LDAh * 2 + kk * 2);
#pragma unroll
            for (int nb = 0; nb < 4; nb++)
                ldsm_x4(bf[nb], sb + TILEA + b_off + nb * 16 * LDAh * 2 + kk * 2);
#pragma unroll
            for (int mi = 0; mi < 4; mi++)
#pragma unroll
                for (int nb = 0; nb < 4; nb++) {
                    mma16816h(acc[mi][nb * 2 + 0], ah[mi], &bf[nb][0]);
                    mma16816h(acc[mi][nb * 2 + 1], ah[mi], &bf[nb][2]);
                }
        }

        if (s + 1 < S) {
            char* bb = smc + ((s + 1) & 1) * STAGEB;
            *(uint4*)(bb + soffA0) = rg[0];
            *(uint4*)(bb + soffA1) = rg[1];
#pragma unroll
            for (int i = 0; i < 4; i++)
                *(uint4*)(bb + TILEA + ((ldrow + i * 64) * LDAh + ldq * 8) * 2) = rg[2 + i];
        }
        __syncthreads();
    }

    int frow = lane >> 2;
    int fcol = (lane & 3) * 2;
#pragma unroll
    for (int mi = 0; mi < 4; mi++) {
#pragma unroll
        for (int ni = 0; ni < 8; ni++) {
            int row = m0 + wm * 64 + mi * 16 + frow;
            int col = n0 + wn * 64 + ni * 8 + fcol;
            *(float2*)(C + (size_t)row * N + col) = make_float2(acc[mi][ni][0], acc[mi][ni][1]);
            *(float2*)(C + (size_t)(row + 8) * N + col) = make_float2(acc[mi][ni][2], acc[mi][ni][3]);
        }
    }
}

// ---------------- beta = sigmoid(x @ Wb) + x -> fp16 ----------------
__global__ void beta_xh_kernel(const float* __restrict__ x, const float* __restrict__ Wb) {
    int gw   = (blockIdx.x << 3) + (threadIdx.x >> 5);
    int lane = threadIdx.x & 31;
    const float* xr = x + (size_t)gw * HIDv;
    __half* xhr = g_xh + (size_t)gw * HIDv;
    float a0 = 0.f, a1 = 0.f, a2 = 0.f, a3 = 0.f;
    for (int r = lane; r < HIDv; r += 32) {
        float xv = xr[r];
        xhr[r] = __float2half(xv);
        const float* wb = Wb + r * 4;
        a0 += xv * wb[0]; a1 += xv * wb[1]; a2 += xv * wb[2]; a3 += xv * wb[3];
    }
    for (int o = 16; o; o >>= 1) {
        a0 += __shfl_xor_sync(0xffffffffu, a0, o);
        a1 += __shfl_xor_sync(0xffffffffu, a1, o);
        a2 += __shfl_xor_sync(0xffffffffu, a2, o);
        a3 += __shfl_xor_sync(0xffffffffu, a3, o);
    }
    if (!lane) {
        float* bp = &g_beta[gw * 4];
        bp[0] = 1.f / (1.f + expf(-a0));
        bp[1] = 1.f / (1.f + expf(-a1));
        bp[2] = 1.f / (1.f + expf(-a2));
        bp[3] = 1.f / (1.f + expf(-a3));
    }
}

// src [K][N] fp32 -> dst [N][K] fp16; 2-way z select
__global__ void htrans2_kernel(const float* __restrict__ s0, const float* __restrict__ s1,
                               __half* __restrict__ h0, __half* __restrict__ h1,
                               int K, int N) {
    __shared__ float tile[32][33];
    int z = blockIdx.z;
    const float* src = z ? s1 : s0;
    __half* hi = z ? h1 : h0;
    int k0 = blockIdx.y * 32;
    int n0 = blockIdx.x * 32;
    int tx = threadIdx.x & 31;
    int ty = threadIdx.x >> 5;
    for (int r = ty; r < 32; r += 8) tile[r][tx] = src[(size_t)(k0 + r) * N + n0 + tx];
    __syncthreads();
    for (int r = ty; r < 32; r += 8)
        hi[(size_t)(n0 + r) * K + k0 + tx] = __float2half(tile[tx][r]);
}

// 4 fused 1024x1024 weight transposes
__global__ void htrans4_kernel(const float* __restrict__ s0, const float* __restrict__ s1,
                               const float* __restrict__ s2, const float* __restrict__ s3,
                               __half* __restrict__ h0, __half* __restrict__ h1,
                               __half* __restrict__ h2, __half* __restrict__ h3) {
    __shared__ float tile[32][33];
    int z = blockIdx.z;
    const float* src = (z == 0) ? s0 : (z == 1) ? s1 : (z == 2) ? s2 : s3;
    __half* hi = (z == 0) ? h0 : (z == 1) ? h1 : (z == 2) ? h2 : h3;
    int k0 = blockIdx.y * 32;
    int n0 = blockIdx.x * 32;
    int tx = threadIdx.x & 31;
    int ty = threadIdx.x >> 5;
    for (int r = ty; r < 32; r += 8) tile[r][tx] = src[(size_t)(k0 + r) * 1024 + n0 + tx];
    __syncthreads();
    for (int r = ty; r < 32; r += 8)
        hi[(size_t)(n0 + r) * 1024 + k0 + tx] = __float2half(tile[tx][r]);
}

// ---------------- tiled FIR reading precomputed v (writes P + Ph) ----------------
#define FIR_SMEM ((46 * 256 + 31 * 256 + 3 * 256) * 4)
__global__ __launch_bounds__(256) void fir_tiled_kernel(const float* __restrict__ fs,
                                                        const float* __restrict__ fl) {
    float* vwin = (float*)dynsm;
    float* flm  = vwin + 46 * 256;
    float* fsm  = flm + 31 * 256;

    int t = threadIdx.x;
    int lt = blockIdx.x & 63;
    int bh = blockIdx.x >> 6;
    int h = bh & 3;
    int b = bh >> 2;
    int l0 = lt * 16;

    for (int idx = t; idx < 256 * 31; idx += 256) flm[idx] = fl[(size_t)h * 256 * 31 + idx];
    for (int idx = t; idx < 256 * 3; idx += 256)  fsm[idx] = fs[(size_t)h * 256 * 3 + idx];
    for (int r = 0; r < 46; r++) {
        int l = l0 - 30 + r;
        vwin[r * 256 + t] = (l >= 0) ? g_v[(((size_t)b * Ll + l) * NHh + h) * 256 + t] : 0.f;
    }
    __syncthreads();

    const float* myfl = &flm[t * 31];
    const float* myfs = &fsm[t * 3];
    for (int li = 0; li < 16; li++) {
        float accL = 0.f;
#pragma unroll
        for (int j = 0; j < 31; j++) accL += vwin[(li + j) * 256 + t] * myfl[j];
        float accS = vwin[(li + 28) * 256 + t] * myfs[0]
                   + vwin[(li + 29) * 256 + t] * myfs[1]
                   + vwin[(li + 30) * 256 + t] * myfs[2];
        float vcur = vwin[(li + 30) * 256 + t];
        size_t row = ((size_t)b * Ll + l0 + li) * NHh + h;
        g_P [(row * 4 + 0) * 256 + t] = accS;
        g_P [(row * 4 + 1) * 256 + t] = accL;
        g_P [(row * 4 + 3) * 256 + t] = vcur;
        g_Ph[(row * 4 + 0) * 256 + t] = __float2half(accS);
        g_Ph[(row * 4 + 1) * 256 + t] = __float2half(accL);
        g_Ph[(row * 4 + 3) * 256 + t] = __float2half(vcur);
    }
}

// ---------------- delta pre (inline conv; emits v; 2 CTA/SM) ----------------
#define PADP 260
#define PRE_SMEM ((3 * 32 * PADP + 1024 + 1056 + 96) * 4)   // 108544 B

__global__ __launch_bounds__(256, 2) void delta_pre_kernel(const float* __restrict__ qc,
                                                           const float* __restrict__ kc,
                                                           const float* __restrict__ vc) {
    float* smf = (float*)dynsm;
    float* qs  = smf;
    float* kn  = qs + 32 * PADP;
    float* vb  = kn + 32 * PADP;
    float* Am  = vb + 32 * PADP;
    float* Tm  = Am + 1024;
    float* bet = Tm + 1056;
    float* rsq = bet + 32;
    float* rsk = rsq + 32;

    int t  = threadIdx.x;
    int n  = blockIdx.x & 31;
    int bh = blockIdx.x >> 5;
    int h  = bh & 3;
    int b  = bh >> 2;
    int l0 = n * CHh;
    size_t obase = ((((size_t)b * NHh + h) * NCc + n) * CHh) * 256;

    // inline conv+silu staging from qkvlin; also emit v for FIR
    {
        int d = (t & 63) << 2;
        int c4 = t >> 6;
        int chq = h * 256 + d;
        float4 wq[4], wk[4], wv[4];
#pragma unroll
        for (int i = 0; i < 4; i++) {
            wq[i] = *(const float4*)(qc + (size_t)(chq + i) * 4);
            wk[i] = *(const float4*)(kc + (size_t)(chq + i) * 4);
            wv[i] = *(const float4*)(vc + (size_t)(chq + i) * 4);
        }
#pragma unroll
        for (int k8 = 0; k8 < 8; k8++) {
            int c = c4 + 4 * k8;
            int l = l0 + c;
            float4 aq = make_float4(0.f, 0.f, 0.f, 0.f);
            float4 ak = aq, av = aq;
#pragma unroll
            for (int j = 0; j < 4; j++) {
                int ls = l - 3 + j;
                if (ls >= 0) {
                    const float* rowp = g_qkvlin + (size_t)(b * Ll + ls) * 3072 + chq;
                    float4 xq = *(const float4*)(rowp);
                    float4 xk = *(const float4*)(rowp + 1024);
                    float4 xv = *(const float4*)(rowp + 2048);
                    aq.x += xq.x * f4c(wq[0], j); aq.y += xq.y * f4c(wq[1], j);
                    aq.z += xq.z * f4c(wq[2], j); aq.w += xq.w * f4c(wq[3], j);
                    ak.x += xk.x * f4c(wk[0], j); ak.y += xk.y * f4c(wk[1], j);
                    ak.z += xk.z * f4c(wk[2], j); ak.w += xk.w * f4c(wk[3], j);
                    av.x += xv.x * f4c(wv[0], j); av.y += xv.y * f4c(wv[1], j);
                    av.z += xv.z * f4c(wv[2], j); av.w += xv.w * f4c(wv[3], j);
                }
            }
            aq.x = silu(aq.x); aq.y = silu(aq.y); aq.z = silu(aq.z); aq.w = silu(aq.w);
            ak.x = silu(ak.x); ak.y = silu(ak.y); ak.z = silu(ak.z); ak.w = silu(ak.w);
            av.x = silu(av.x); av.y = silu(av.y); av.z = silu(av.z); av.w = silu(av.w);
            *(float4*)(&qs[c * PADP + d]) = aq;
            *(float4*)(&kn[c * PADP + d]) = ak;
            *(float4*)(&vb[c * PADP + d]) = av;
            *(float4*)(&g_v[(((size_t)b * Ll + l) * NHh + h) * 256 + d]) = av;
        }
    }
    if (t < CHh) bet[t] = g_beta[((size_t)b * Ll + l0 + t) * NHh + h];
    __syncthreads();

    int lane = t & 31;
    int wid = t >> 5;
    for (int r = wid; r < CHh; r += 8) {
        float sq = 0.f, sk = 0.f;
        for (int d = lane; d < 256; d += 32) {
            float a = qs[r * PADP + d]; sq += a * a;
            float c2 = kn[r * PADP + d]; sk += c2 * c2;
        }
        for (int o = 16; o; o >>= 1) {
            sq += __shfl_xor_sync(0xffffffffu, sq, o);
            sk += __shfl_xor_sync(0xffffffffu, sk, o);
        }
        if (!lane) { rsq[r] = rsqrtf(sq + 1e-6f); rsk[r] = rsqrtf(sk + 1e-6f); }
    }
    __syncthreads();

    for (int idx = t; idx < 32 * 64; idx += 256) {
        int c = idx >> 6;
        int d = (idx & 63) << 2;
        float4 qv = *(float4*)(&qs[c * PADP + d]);
        float4 kv = *(float4*)(&kn[c * PADP + d]);
        float4 vv = *(float4*)(&vb[c * PADP + d]);
        float rq = rsq[c], rk = rsk[c], bb2 = bet[c];
        qv.x *= rq; qv.y *= rq; qv.z *= rq; qv.w *= rq;
        kv.x *= rk; kv.y *= rk; kv.z *= rk; kv.w *= rk;
        vv.x *= bb2; vv.y *= bb2; vv.z *= bb2; vv.w *= bb2;
        *(float4*)(&qs[c * PADP + d]) = qv;
        *(float4*)(&kn[c * PADP + d]) = kv;
        *(float4*)(&vb[c * PADP + d]) = vv;
        *(float4*)(&g_qn[obase + c * 256 + d]) = qv;
        *(float4*)(&g_kn[obase + c * 256 + d]) = kv;
    }
    __syncthreads();

    // attn/A: 2x2 register-tiled float4 dot products
    {
        int ti = t >> 4;
        int tj = t & 15;
        const float* qA = &qs[ti * PADP];
        const float* qB = &qs[(ti + 16) * PADP];
        const float* kI0 = &kn[ti * PADP];
        const float* kI1 = &kn[(ti + 16) * PADP];
        const float* kJ0 = &kn[tj * PADP];
        const float* kJ1 = &kn[(tj + 16) * PADP];
        float dq00 = 0.f, dq01 = 0.f, dq10 = 0.f, dq11 = 0.f;
        float dk00 = 0.f, dk01 = 0.f, dk10 = 0.f, dk11 = 0.f;
#pragma unroll 4
        for (int d4 = 0; d4 < 64; d4++) {
            int d = d4 << 2;
            float4 a0 = *(const float4*)(&qA[d]);
            float4 a1 = *(const float4*)(&qB[d]);
            float4 b0 = *(const float4*)(&kJ0[d]);
            float4 b1 = *(const float4*)(&kJ1[d]);
            float4 c0 = *(const float4*)(&kI0[d]);
            float4 c1 = *(const float4*)(&kI1[d]);
            dq00 += a0.x * b0.x; dq00 += a0.y * b0.y; dq00 += a0.z * b0.z; dq00 += a0.w * b0.w;
            dq01 += a0.x * b1.x; dq01 += a0.y * b1.y; dq01 += a0.z * b1.z; dq01 += a0.w * b1.w;
            dq10 += a1.x * b0.x; dq10 += a1.y * b0.y; dq10 += a1.z * b0.z; dq10 += a1.w * b0.w;
            dq11 += a1.x * b1.x; dq11 += a1.y * b1.y; dq11 += a1.z * b1.z; dq11 += a1.w * b1.w;
            dk00 += c0.x * b0.x; dk00 += c0.y * b0.y; dk00 += c0.z * b0.z; dk00 += c0.w * b0.w;
            dk01 += c0.x * b1.x; dk01 += c0.y * b1.y; dk01 += c0.z * b1.z; dk01 += c0.w * b1.w;
            dk10 += c1.x * b0.x; dk10 += c1.y * b0.y; dk10 += c1.z * b0.z; dk10 += c1.w * b0.w;
            dk11 += c1.x * b1.x; dk11 += c1.y * b1.y; dk11 += c1.z * b1.z; dk11 += c1.w * b1.w;
        }
        size_t abase = ((((size_t)b * NHh + h) * NCc + n) << 10);
        int i0 = ti, i1 = ti + 16, j0 = tj, j1 = tj + 16;
        float bi0 = bet[i0], bi1 = bet[i1];
        Am[i0 * 32 + j0] = (j0 < i0) ? (-bi0 * dk00) : 0.f;
        Am[i0 * 32 + j1] = (j1 < i0) ? (-bi0 * dk01) : 0.f;
        Am[i1 * 32 + j0] = (j0 < i1) ? (-bi1 * dk10) : 0.f;
        Am[i1 * 32 + j1] = (j1 < i1) ? (-bi1 * dk11) : 0.f;
        g_attn[abase + i0 * 32 + j0] = (j0 <= i0) ? dq00 : 0.f;
        g_attn[abase + i0 * 32 + j1] = (j1 <= i0) ? dq01 : 0.f;
        g_attn[abase + i1 * 32 + j0] = (j0 <= i1) ? dq10 : 0.f;
        g_attn[abase + i1 * 32 + j1] = (j1 <= i1) ? dq11 : 0.f;
    }
    __syncthreads();

    if (t < 32) {
        Tm[t] = (t == 0) ? 1.f : 0.f;
        for (int i = 1; i < 32; i++) {
            float acc = (i == t) ? 1.f : 0.f;
            for (int m = 0; m < i; m++) acc += Am[i * 32 + m] * Tm[m * 33 + t];
            Tm[i * 33 + t] = acc;
        }
    }
    __syncthreads();

    {
        int d = t;
        float vbr[32], knr[32];
#pragma unroll
        for (int m = 0; m < 32; m++) {
            vbr[m] = vb[m * PADP + d];
            knr[m] = kn[m * PADP + d] * bet[m];
        }
#pragma unroll
        for (int r = 0; r < 32; r++) {
            float au = 0.f, aw = 0.f;
#pragma unroll
            for (int m = 0; m < 32; m++) {
                if (m <= r) {
                    float tv = Tm[r * 33 + m];
                    au += tv * vbr[m];
                    aw += tv * knr[m];
                }
            }
            g_u[obase + r * 256 + d] = au;
            g_w[obase + r * 256 + d] = aw;
        }
    }
}

// ---------------- serial chunk scan: 512 threads, thread = (c, j) ----------------
#define KST 272
__global__ __launch_bounds__(512) void scan_kernel() {
    float* smf = (float*)dynsm;
    float* S  = smf;             // 256*17
    float* qn = S + 4352;        // 32*272
    float* kn = qn + 8704;
    float* wS = kn + 8704;
    float* un = wS + 8704;       // 32*17
    float* uu = un + 544;        // 32*16
    float* at = uu + 512;        // 32*33

    int t = threadIdx.x;
    int s_idx = blockIdx.x & 15;
    int bh = blockIdx.x >> 4;
    int h = bh & 3;
    int b = bh >> 2;
    int j0 = s_idx * 16;

    for (int i = t; i < 4352; i += 512) S[i] = 0.f;
    __syncthreads();

    int j = t & 15;
    int c = t >> 4;              // 0..31 (one chunk-row per thread)

    for (int n = 0; n < NCc; n++) {
        size_t base = ((((size_t)b * NHh + h) * NCc + n) * CHh) * 256;
        for (int idx = t; idx < 32 * 64; idx += 512) {
            int cc = idx >> 6;
            int dq = (idx & 63) << 2;
            *(float4*)(&qn[cc * KST + dq]) = *(const float4*)(&g_qn[base + cc * 256 + dq]);
            *(float4*)(&kn[cc * KST + dq]) = *(const float4*)(&g_kn[base + cc * 256 + dq]);
            *(float4*)(&wS[cc * KST + dq]) = *(const float4*)(&g_w [base + cc * 256 + dq]);
        }
        uu[c * 16 + j] = g_u[base + c * 256 + j0 + j];
        size_t abase = ((((size_t)b * NHh + h) * NCc + n) << 10);
        for (int idx = t; idx < 1024; idx += 512) {
            int cc = idx >> 5;
            int cp = idx & 31;
            at[cc * 33 + cp] = g_attn[abase + idx];
        }
        __syncthreads();

        // merged pass: one (c, j) per thread
        float a = uu[c * 16 + j];
        float o = 0.f;
        const float* wr = &wS[c * KST];
        const float* qr = &qn[c * KST];
#pragma unroll 8
        for (int d4 = 0; d4 < 64; d4++) {
            int d = d4 << 2;
            float4 wv = *(const float4*)(&wr[d]);
            float4 qv = *(const float4*)(&qr[d]);
            float s0 = S[(d + 0) * 17 + j];
            float s1 = S[(d + 1) * 17 + j];
            float s2 = S[(d + 2) * 17 + j];
            float s3 = S[(d + 3) * 17 + j];
            a -= wv.x * s0 + wv.y * s1 + wv.z * s2 + wv.w * s3;
            o += qv.x * s0 + qv.y * s1 + qv.z * s2 + qv.w * s3;
        }
        un[c * 17 + j] = a;
        __syncthreads();

        for (int cp = 0; cp <= c; cp++) o += at[c * 33 + cp] * un[cp * 17 + j];
        {
            int l = n * CHh + c;
            size_t r0 = (((size_t)b * Ll + l) * NHh + h) * 4 + 2;
            g_P [r0 * 256 + j0 + j] = o;
            g_Ph[r0 * 256 + j0 + j] = __float2half(o);
        }

        // S update: thread owns 8 d's (c*8 .. c*8+7) for its column j
#pragma unroll
        for (int blk = 0; blk < 2; blk++) {
            int d0 = c * 8 + blk * 4;
            float s0 = S[(d0 + 0) * 17 + j];
            float s1 = S[(d0 + 1) * 17 + j];
            float s2 = S[(d0 + 2) * 17 + j];
            float s3 = S[(d0 + 3) * 17 + j];
            for (int cc = 0; cc < 32; cc++) {
                float u = un[cc * 17 + j];
                float4 kv = *(const float4*)(&kn[cc * KST + d0]);
                s0 += kv.x * u; s1 += kv.y * u; s2 += kv.z * u; s3 += kv.w * u;
            }
            S[(d0 + 0) * 17 + j] = s0;
            S[(d0 + 1) * 17 + j] = s1;
            S[(d0 + 2) * 17 + j] = s2;
            S[(d0 + 3) * 17 + j] = s3;
        }
        __syncthreads();
    }
}

// ---------------- gW1 stat-block column sums ----------------
__global__ void ssum_kernel(const float* __restrict__ gW1) {
    int idx = blockIdx.x * 256 + threadIdx.x;
    int s12 = idx / GHh;
    int nn = idx % GHh;
    float a = 0.f;
    const float* base = gW1 + (size_t)(1024 + s12 * 256) * GHh + nn;
    for (int r = 0; r < 256; r++) a += base[(size_t)r * GHh];
    g_ssum[idx] = a;
}

// ---------------- gate finalize (fused stats; P cached in smem; writes oh) ----------------
__global__ void gate_final_kernel(const float* __restrict__ gb1,
                                  const float* __restrict__ gW2,
                                  const float* __restrict__ gb2,
                                  const float* __restrict__ temp,
                                  const float* __restrict__ epsf,
                                  const float* __restrict__ onw) {
    __shared__ float mid[GHh];
    __shared__ float st[12];
    __shared__ float w4[4];
    __shared__ float red[256];
    __shared__ float rS[256], rQ[256], rM[256];
    __shared__ float Psm[1024];
    int row = blockIdx.x;
    int t = threadIdx.x;
    int h = row & 3;
    int bl = row >> 2;

    {
        int jb = t >> 6;
        int s = t & 63;
        const float* p = &g_P[((size_t)row * 4 + jb) << 8];
        float sm = 0.f, sq = 0.f, mx = -3.4e38f;
#pragma unroll
        for (int k = 0; k < 4; k++) {
            float v = p[s + 64 * k];
            Psm[jb * 256 + s + 64 * k] = v;
            sm += v; sq += v * v; mx = fmaxf(mx, v);
        }
        rS[t] = sm; rQ[t] = sq; rM[t] = mx;
        __syncthreads();
        for (int str = 32; str >= 1; str >>= 1) {
            if (s < str) {
                rS[t] += rS[t + str];
                rQ[t] += rQ[t + str];
                rM[t] = fmaxf(rM[t], rM[t + str]);
            }
            __syncthreads();
        }
        if (s == 0) {
            st[jb * 3 + 0] = rS[t] * (1.f / 256.f);
            st[jb * 3 + 1] = sqrtf(fmaxf(rQ[t] * (1.f / 256.f), 1e-8f));
            st[jb * 3 + 2] = rM[t];
        }
        __syncthreads();
    }

    for (int nn = t; nn < GHh; nn += 256) {
        float val = g_hid1[(size_t)bl * GHh + nn] + g_bpart[(size_t)row * GHh + nn] + gb1[nn];
#pragma unroll
        for (int s12 = 0; s12 < 12; s12++) val += st[s12] * g_ssum[s12 * GHh + nn];
        mid[nn] = 0.5f * val * (1.f + erff(val * 0.70710678118654752f));
    }
    __syncthreads();

    {
        int o = t & 3;
        float p = 0.f;
        for (int nidx = t >> 2; nidx < GHh; nidx += 64) p += mid[nidx] * gW2[nidx * 4 + o];
        red[t] = p;
    }
    __syncthreads();
    if (t < 4) {
        float lg = gb2[t];
        for (int g = 0; g < 64; g++) lg += red[g * 4 + t];
        red[t] = lg;
    }
    __syncthreads();
    if (t == 0) {
        float tc = fminf(fmaxf(temp[h], 0.2f), 10.f);
        float l0 = red[0] / tc, l1 = red[1] / tc, l2 = red[2] / tc, l3 = red[3] / tc;
        float mx = fmaxf(fmaxf(l0, l1), fmaxf(l2, l3));
        float e0 = expf(l0 - mx), e1 = expf(l1 - mx), e2 = expf(l2 - mx), e3 = expf(l3 - mx);
        float s = e0 + e1 + e2 + e3;
        float w0 = e0 / s, w1 = e1 / s, w2 = e2 / s, w3 = e3 / s;
        float f0 = fminf(fmaxf(epsf[h * 4 + 0], 1e-7f), 0.1f);
        float f1 = fminf(fmaxf(epsf[h * 4 + 1], 1e-7f), 0.1f);
        float f2 = fminf(fmaxf(epsf[h * 4 + 2], 1e-7f), 0.1f);
        float f3 = fminf(fmaxf(epsf[h * 4 + 3], 1e-7f), 0.1f);
        w0 = fmaxf(w0, f0); w1 = fmaxf(w1, f1); w2 = fmaxf(w2, f2); w3 = fmaxf(w3, f3);
        float s2 = w0 + w1 + w2 + w3;
        w4[0] = w0 / s2; w4[1] = w1 / s2; w4[2] = w2 / s2; w4[3] = w3 / s2;
    }
    __syncthreads();

    float od = 0.f;
#pragma unroll
    for (int jj = 0; jj < 4; jj++) od += w4[jj] * Psm[jj * 256 + t];
    red[t] = od * od;
    __syncthreads();
    for (int s = 128; s > 0; s >>= 1) {
        if (t < s) red[t] += red[t + s];
        __syncthreads();
    }
    float ms = red[0] * (1.f / 256.f);
    g_oh[(size_t)bl * HIDv + h * 256 + t] = __float2half(od * rsqrtf(ms + 1e-5f) * onw[t]);
}

// ---------------- host launcher ----------------
static const int SCAN_SMEM = 32576 * 4;

extern "C" void kernel_launch(void* const* d_in, const int* in_sizes, int n_in,
                              void* d_out, int out_size) {
    const float *x = 0, *Wq = 0, *Wk = 0, *Wv = 0, *Wb = 0, *qc = 0, *kc = 0, *vc = 0;
    const float *firs = 0, *firl = 0, *gW1 = 0, *gb1 = 0, *gW2 = 0, *gb2 = 0;
    const float *temp = 0, *epsf = 0, *onw = 0, *Wo = 0;
    int occ1M = 0, occ4k = 0, occ4 = 0;
    for (int i = 0; i < n_in; i++) {
        const float* p = (const float*)d_in[i];
        switch (in_sizes[i]) {
            case 2097152: x = p; break;
            case 1048576:
                if (occ1M == 0) Wq = p; else if (occ1M == 1) Wk = p;
                else if (occ1M == 2) Wv = p; else Wo = p;
                occ1M++; break;
            case 4096:
                if (occ4k == 0) Wb = p; else if (occ4k == 1) qc = p;
                else if (occ4k == 2) kc = p; else vc = p;
                occ4k++; break;
            case 2621440: gW1 = p; break;
            case 512:     gb1 = p; break;
            case 2048:    gW2 = p; break;
            case 4:       if (occ4 == 0) gb2 = p; else temp = p; occ4++; break;
            case 16:      epsf = p; break;
            case 256:     onw = p; break;
            case 3072:    firs = p; break;
            case 31744:   firl = p; break;
            default: break;
        }
    }

    float *p_qkvlin, *p_hid1, *p_bpart;
    cudaGetSymbolAddress((void**)&p_qkvlin, g_qkvlin);
    cudaGetSymbolAddress((void**)&p_hid1, g_hid1);
    cudaGetSymbolAddress((void**)&p_bpart, g_bpart);

    __half *xh, *Ph, *oh, *Wqkvh, *Woh, *g1ah, *g1bh;
    cudaGetSymbolAddress((void**)&xh, g_xh);
    cudaGetSymbolAddress((void**)&Ph, g_Ph);
    cudaGetSymbolAddress((void**)&oh, g_oh);
    cudaGetSymbolAddress((void**)&Wqkvh, g_Wqkvh);
    cudaGetSymbolAddress((void**)&Woh, g_Woh);
    cudaGetSymbolAddress((void**)&g1ah, g_g1ah);
    cudaGetSymbolAddress((void**)&g1bh, g_g1bh);

    cudaFuncSetAttribute(delta_pre_kernel, cudaFuncAttributeMaxDynamicSharedMemorySize, PRE_SMEM);
    cudaFuncSetAttribute(scan_kernel, cudaFuncAttributeMaxDynamicSharedMemorySize, SCAN_SMEM);
    cudaFuncSetAttribute(gemm_fp16, cudaFuncAttributeMaxDynamicSharedMemorySize, GEMM_SMEM);
    cudaFuncSetAttribute(fir_tiled_kernel, cudaFuncAttributeMaxDynamicSharedMemorySize, FIR_SMEM);

    const size_t W1M = (size_t)1024 * 1024;

    // single stream; launch #4 = merged QKV GEMM (profiled)
    beta_xh_kernel<<<256, 256>>>(x, Wb);                                          // 1
    htrans4_kernel<<<dim3(32, 32, 4), 256>>>(Wq, Wk, Wv, Wo,
        Wqkvh, Wqkvh + W1M, Wqkvh + 2 * W1M, Woh);                                // 2
    htrans2_kernel<<<dim3(16, 32, 2), 256>>>(gW1, gW1 + (size_t)4096 * 512,
                                             g1ah, g1bh, 1024, 512);              // 3
    gemm_fp16<<<dim3(12, 16), 256, GEMM_SMEM>>>(xh, Wqkvh, p_qkvlin, 2048, 3072, 1024);  // 4 <- profiled
    ssum_kernel<<<24, 256>>>(gW1);                                                // 5
    delta_pre_kernel<<<256, 256, PRE_SMEM>>>(qc, kc, vc);                         // 6
    scan_kernel<<<128, 512, SCAN_SMEM>>>();                                       // 7
    fir_tiled_kernel<<<512, 256, FIR_SMEM>>>(firs, firl);                         // 8
    gemm_fp16<<<dim3(2, 16), 256, GEMM_SMEM>>>(xh, g1ah, p_hid1, 2048, 512, 1024);        // 9
    gemm_fp16<<<dim3(2, 64), 256, GEMM_SMEM>>>(Ph, g1bh, p_bpart, 8192, 512, 1024);       // 10
    gate_final_kernel<<<8192, 256>>>(gb1, gW2, gb2, temp, epsf, onw);             // 11
    gemm_fp16<<<dim3(4, 16), 256, GEMM_SMEM>>>(oh, Woh, (float*)d_out, 2048, 1024, 1024); // 12
}

// round 17
// speedup vs baseline: 1.1487x; 1.0602x over previous
#include <cuda_runtime.h>
#include <cuda_fp16.h>
#include <stdint.h>
#include <math.h>

// ---------------- problem constants ----------------
#define Bb   2
#define Ll   1024
#define HIDv 1024
#define NHh  4
#define DKk  256
#define NCc  32
#define CHh  32
#define BLr  2048
#define GHh  512
#define QKVW 3584   // fused width: q|k|v|hid1

extern __shared__ char dynsm[];

// ---------------- scratch ----------------
__device__ float g_qkvlin[BLr * QKVW];      // [b*l][q|k|v|hid1]
__device__ float g_v[BLr * HIDv];
__device__ float g_beta[BLr * NHh];
__device__ float g_qn[BLr * HIDv];
__device__ float g_kn[BLr * HIDv];
__device__ float g_u[BLr * HIDv];
__device__ float g_w[BLr * HIDv];
__device__ float g_attn[Bb * NHh * NCc * CHh * CHh];
__device__ float g_P[BLr * NHh * 4 * DKk];
__device__ float g_ssum[12 * GHh];
__device__ float g_bpart[BLr * NHh * GHh];

__device__ __half g_xh[BLr * HIDv];
__device__ __half g_Ph[BLr * NHh * 4 * DKk];
__device__ __half g_oh[BLr * HIDv];
__device__ __half g_Wqkvh[(size_t)QKVW * HIDv];   // [3584][1024]: Wq|Wk|Wv|g1a
__device__ __half g_Woh[HIDv * HIDv];
__device__ __half g_g1bh[GHh * HIDv];

// ---------------- PTX helpers ----------------
__device__ __forceinline__ uint32_t smem_u32(const void* p) {
    uint32_t a;
    asm("{ .reg .u64 t; cvta.to.shared.u64 t, %1; cvt.u32.u64 %0, t; }" : "=r"(a) : "l"(p));
    return a;
}
__device__ __forceinline__ void ldsm_x4(uint32_t* r, uint32_t addr) {
    asm volatile("ldmatrix.sync.aligned.m8n8.x4.shared.b16 {%0,%1,%2,%3}, [%4];"
                 : "=r"(r[0]), "=r"(r[1]), "=r"(r[2]), "=r"(r[3]) : "r"(addr));
}
__device__ __forceinline__ void mma16816h(float* d, const uint32_t* a, const uint32_t* b) {
    asm volatile(
        "mma.sync.aligned.m16n8k16.row.col.f32.f16.f16.f32 "
        "{%0,%1,%2,%3}, {%4,%5,%6,%7}, {%8,%9}, {%0,%1,%2,%3};"
        : "+f"(d[0]), "+f"(d[1]), "+f"(d[2]), "+f"(d[3])
        : "r"(a[0]), "r"(a[1]), "r"(a[2]), "r"(a[3]), "r"(b[0]), "r"(b[1]));
}
__device__ __forceinline__ float f4c(const float4& v, int j) {
    return j == 0 ? v.x : j == 1 ? v.y : j == 2 ? v.z : v.w;
}
__device__ __forceinline__ float silu(float z) {
    return z / (1.f + expf(-z));
}

// ---------------- single-term fp16 HMMA GEMM (R12-proven) ----------------
#define LDAh 40
#define TILEA (128 * LDAh * 2)
#define TILEBB (256 * LDAh * 2)
#define STAGEB (TILEA + TILEBB)
#define GEMM_SMEM (2 * STAGEB)

__global__ __launch_bounds__(256, 1) void gemm_fp16(
    const __half* __restrict__ A, const __half* __restrict__ B,
    float* __restrict__ C, int M, int N, int K) {
    char* smc = dynsm;
    uint32_t sbase = smem_u32(smc);
    int t = threadIdx.x;
    int lane = t & 31;
    int wid = t >> 5;
    int wm = wid & 1;
    int wn = wid >> 1;
    int m0 = blockIdx.y * 128;
    int n0 = blockIdx.x * 256;

    float acc[4][8][4];
#pragma unroll
    for (int i = 0; i < 4; i++)
#pragma unroll
        for (int j = 0; j < 8; j++)
#pragma unroll
            for (int c = 0; c < 4; c++) acc[i][j][c] = 0.f;

    uint4 rg[6];
    int ldrow = t >> 2;
    int ldq = t & 3;
    int soffA0 = ((ldrow)      * LDAh + ldq * 8) * 2;
    int soffA1 = ((ldrow + 64) * LDAh + ldq * 8) * 2;

    int a_off = ((wm * 64 + (lane & 15)) * LDAh + ((lane >> 4) << 3)) * 2;
    int b_off = ((wn * 64 + (lane & 7) + ((lane >> 4) << 3)) * LDAh + (((lane >> 3) & 1) << 3)) * 2;

    const int S = K / 32;

    {
        rg[0] = *(const uint4*)(A + (size_t)(m0 + ldrow) * K + ldq * 8);
        rg[1] = *(const uint4*)(A + (size_t)(m0 + ldrow + 64) * K + ldq * 8);
#pragma unroll
        for (int i = 0; i < 4; i++)
            rg[2 + i] = *(const uint4*)(B + (size_t)(n0 + ldrow + i * 64) * K + ldq * 8);
    }
    *(uint4*)(smc + soffA0) = rg[0];
    *(uint4*)(smc + soffA1) = rg[1];
#pragma unroll
    for (int i = 0; i < 4; i++)
        *(uint4*)(smc + TILEA + ((ldrow + i * 64) * LDAh + ldq * 8) * 2) = rg[2 + i];
    __syncthreads();

    for (int s = 0; s < S; s++) {
        int cur = s & 1;
        if (s + 1 < S) {
            int k0 = (s + 1) * 32;
            rg[0] = *(const uint4*)(A + (size_t)(m0 + ldrow) * K + k0 + ldq * 8);
            rg[1] = *(const uint4*)(A + (size_t)(m0 + ldrow + 64) * K + k0 + ldq * 8);
#pragma unroll
            for (int i = 0; i < 4; i++)
                rg[2 + i] = *(const uint4*)(B + (size_t)(n0 + ldrow + i * 64) * K + k0 + ldq * 8);
        }

        uint32_t sb = sbase + cur * STAGEB;
#pragma unroll
        for (int kk = 0; kk < 32; kk += 16) {
            uint32_t ah[4][4], bf[4][4];
#pragma unroll
            for (int mi = 0; mi < 4; mi++)
                ldsm_x4(ah[mi], sb + a_off + mi * 16 * LDAh * 2 + kk * 2);
#pragma unroll
            for (int nb = 0; nb < 4; nb++)
                ldsm_x4(bf[nb], sb + TILEA + b_off + nb * 16 * LDAh * 2 + kk * 2);
#pragma unroll
            for (int mi = 0; mi < 4; mi++)
#pragma unroll
                for (int nb = 0; nb < 4; nb++) {
                    mma16816h(acc[mi][nb * 2 + 0], ah[mi], &bf[nb][0]);
                    mma16816h(acc[mi][nb * 2 + 1], ah[mi], &bf[nb][2]);
                }
        }

        if (s + 1 < S) {
            char* bb = smc + ((s + 1) & 1) * STAGEB;
            *(uint4*)(bb + soffA0) = rg[0];
            *(uint4*)(bb + soffA1) = rg[1];
#pragma unroll
            for (int i = 0; i < 4; i++)
                *(uint4*)(bb + TILEA + ((ldrow + i * 64) * LDAh + ldq * 8) * 2) = rg[2 + i];
        }
        __syncthreads();
    }

    int frow = lane >> 2;
    int fcol = (lane & 3) * 2;
#pragma unroll
    for (int mi = 0; mi < 4; mi++) {
#pragma unroll
        for (int ni = 0; ni < 8; ni++) {
            int row = m0 + wm * 64 + mi * 16 + frow;
            int col = n0 + wn * 64 + ni * 8 + fcol;
            *(float2*)(C + (size_t)row * N + col) = make_float2(acc[mi][ni][0], acc[mi][ni][1]);
            *(float2*)(C + (size_t)(row + 8) * N + col) = make_float2(acc[mi][ni][2], acc[mi][ni][3]);
        }
    }
}

// ---------------- beta = sigmoid(x @ Wb) + x -> fp16 ----------------
__global__ void beta_xh_kernel(const float* __restrict__ x, const float* __restrict__ Wb) {
    int gw   = (blockIdx.x << 3) + (threadIdx.x >> 5);
    int lane = threadIdx.x & 31;
    const float* xr = x + (size_t)gw * HIDv;
    __half* xhr = g_xh + (size_t)gw * HIDv;
    float a0 = 0.f, a1 = 0.f, a2 = 0.f, a3 = 0.f;
    for (int r = lane; r < HIDv; r += 32) {
        float xv = xr[r];
        xhr[r] = __float2half(xv);
        const float* wb = Wb + r * 4;
        a0 += xv * wb[0]; a1 += xv * wb[1]; a2 += xv * wb[2]; a3 += xv * wb[3];
    }
    for (int o = 16; o; o >>= 1) {
        a0 += __shfl_xor_sync(0xffffffffu, a0, o);
        a1 += __shfl_xor_sync(0xffffffffu, a1, o);
        a2 += __shfl_xor_sync(0xffffffffu, a2, o);
        a3 += __shfl_xor_sync(0xffffffffu, a3, o);
    }
    if (!lane) {
        float* bp = &g_beta[gw * 4];
        bp[0] = 1.f / (1.f + expf(-a0));
        bp[1] = 1.f / (1.f + expf(-a1));
        bp[2] = 1.f / (1.f + expf(-a2));
        bp[3] = 1.f / (1.f + expf(-a3));
    }
}

// src [K][N] fp32 -> dst [N][K] fp16; 2-way z select
__global__ void htrans2_kernel(const float* __restrict__ s0, const float* __restrict__ s1,
                               __half* __restrict__ h0, __half* __restrict__ h1,
                               int K, int N) {
    __shared__ float tile[32][33];
    int z = blockIdx.z;
    const float* src = z ? s1 : s0;
    __half* hi = z ? h1 : h0;
    int k0 = blockIdx.y * 32;
    int n0 = blockIdx.x * 32;
    int tx = threadIdx.x & 31;
    int ty = threadIdx.x >> 5;
    for (int r = ty; r < 32; r += 8) tile[r][tx] = src[(size_t)(k0 + r) * N + n0 + tx];
    __syncthreads();
    for (int r = ty; r < 32; r += 8)
        hi[(size_t)(n0 + r) * K + k0 + tx] = __float2half(tile[tx][r]);
}

// 4 fused 1024x1024 weight transposes
__global__ void htrans4_kernel(const float* __restrict__ s0, const float* __restrict__ s1,
                               const float* __restrict__ s2, const float* __restrict__ s3,
                               __half* __restrict__ h0, __half* __restrict__ h1,
                               __half* __restrict__ h2, __half* __restrict__ h3) {
    __shared__ float tile[32][33];
    int z = blockIdx.z;
    const float* src = (z == 0) ? s0 : (z == 1) ? s1 : (z == 2) ? s2 : s3;
    __half* hi = (z == 0) ? h0 : (z == 1) ? h1 : (z == 2) ? h2 : h3;
    int k0 = blockIdx.y * 32;
    int n0 = blockIdx.x * 32;
    int tx = threadIdx.x & 31;
    int ty = threadIdx.x >> 5;
    for (int r = ty; r < 32; r += 8) tile[r][tx] = src[(size_t)(k0 + r) * 1024 + n0 + tx];
    __syncthreads();
    for (int r = ty; r < 32; r += 8)
        hi[(size_t)(n0 + r) * 1024 + k0 + tx] = __float2half(tile[tx][r]);
}

// ---------------- tiled FIR reading precomputed v (writes P + Ph) ----------------
#define FIR_SMEM ((46 * 256 + 31 * 256 + 3 * 256) * 4)
__global__ __launch_bounds__(256) void fir_tiled_kernel(const float* __restrict__ fs,
                                                        const float* __restrict__ fl) {
    float* vwin = (float*)dynsm;
    float* flm  = vwin + 46 * 256;
    float* fsm  = flm + 31 * 256;

    int t = threadIdx.x;
    int lt = blockIdx.x & 63;
    int bh = blockIdx.x >> 6;
    int h = bh & 3;
    int b = bh >> 2;
    int l0 = lt * 16;

    for (int idx = t; idx < 256 * 31; idx += 256) flm[idx] = fl[(size_t)h * 256 * 31 + idx];
    for (int idx = t; idx < 256 * 3; idx += 256)  fsm[idx] = fs[(size_t)h * 256 * 3 + idx];
    for (int r = 0; r < 46; r++) {
        int l = l0 - 30 + r;
        vwin[r * 256 + t] = (l >= 0) ? g_v[(((size_t)b * Ll + l) * NHh + h) * 256 + t] : 0.f;
    }
    __syncthreads();

    const float* myfl = &flm[t * 31];
    const float* myfs = &fsm[t * 3];
    for (int li = 0; li < 16; li++) {
        float accL = 0.f;
#pragma unroll
        for (int j = 0; j < 31; j++) accL += vwin[(li + j) * 256 + t] * myfl[j];
        float accS = vwin[(li + 28) * 256 + t] * myfs[0]
                   + vwin[(li + 29) * 256 + t] * myfs[1]
                   + vwin[(li + 30) * 256 + t] * myfs[2];
        float vcur = vwin[(li + 30) * 256 + t];
        size_t row = ((size_t)b * Ll + l0 + li) * NHh + h;
        g_P [(row * 4 + 0) * 256 + t] = accS;
        g_P [(row * 4 + 1) * 256 + t] = accL;
        g_P [(row * 4 + 3) * 256 + t] = vcur;
        g_Ph[(row * 4 + 0) * 256 + t] = __float2half(accS);
        g_Ph[(row * 4 + 1) * 256 + t] = __float2half(accL);
        g_Ph[(row * 4 + 3) * 256 + t] = __float2half(vcur);
    }
}

// ---------------- delta pre (inline conv from fused qkvlin; emits v; 2 CTA/SM) ----------------
#define PADP 260
#define PRE_SMEM ((3 * 32 * PADP + 1024 + 1056 + 96) * 4)   // 108544 B

__global__ __launch_bounds__(256, 2) void delta_pre_kernel(const float* __restrict__ qc,
                                                           const float* __restrict__ kc,
                                                           const float* __restrict__ vc) {
    float* smf = (float*)dynsm;
    float* qs  = smf;
    float* kn  = qs + 32 * PADP;
    float* vb  = kn + 32 * PADP;
    float* Am  = vb + 32 * PADP;
    float* Tm  = Am + 1024;
    float* bet = Tm + 1056;
    float* rsq = bet + 32;
    float* rsk = rsq + 32;

    int t  = threadIdx.x;
    int n  = blockIdx.x & 31;
    int bh = blockIdx.x >> 5;
    int h  = bh & 3;
    int b  = bh >> 2;
    int l0 = n * CHh;
    size_t obase = ((((size_t)b * NHh + h) * NCc + n) * CHh) * 256;

    {
        int d = (t & 63) << 2;
        int c4 = t >> 6;
        int chq = h * 256 + d;
        float4 wq[4], wk[4], wv[4];
#pragma unroll
        for (int i = 0; i < 4; i++) {
            wq[i] = *(const float4*)(qc + (size_t)(chq + i) * 4);
            wk[i] = *(const float4*)(kc + (size_t)(chq + i) * 4);
            wv[i] = *(const float4*)(vc + (size_t)(chq + i) * 4);
        }
#pragma unroll
        for (int k8 = 0; k8 < 8; k8++) {
            int c = c4 + 4 * k8;
            int l = l0 + c;
            float4 aq = make_float4(0.f, 0.f, 0.f, 0.f);
            float4 ak = aq, av = aq;
#pragma unroll
            for (int j = 0; j < 4; j++) {
                int ls = l - 3 + j;
                if (ls >= 0) {
                    const float* rowp = g_qkvlin + (size_t)(b * Ll + ls) * QKVW + chq;
                    float4 xq = *(const float4*)(rowp);
                    float4 xk = *(const float4*)(rowp + 1024);
                    float4 xv = *(const float4*)(rowp + 2048);
                    aq.x += xq.x * f4c(wq[0], j); aq.y += xq.y * f4c(wq[1], j);
                    aq.z += xq.z * f4c(wq[2], j); aq.w += xq.w * f4c(wq[3], j);
                    ak.x += xk.x * f4c(wk[0], j); ak.y += xk.y * f4c(wk[1], j);
                    ak.z += xk.z * f4c(wk[2], j); ak.w += xk.w * f4c(wk[3], j);
                    av.x += xv.x * f4c(wv[0], j); av.y += xv.y * f4c(wv[1], j);
                    av.z += xv.z * f4c(wv[2], j); av.w += xv.w * f4c(wv[3], j);
                }
            }
            aq.x = silu(aq.x); aq.y = silu(aq.y); aq.z = silu(aq.z); aq.w = silu(aq.w);
            ak.x = silu(ak.x); ak.y = silu(ak.y); ak.z = silu(ak.z); ak.w = silu(ak.w);
            av.x = silu(av.x); av.y = silu(av.y); av.z = silu(av.z); av.w = silu(av.w);
            *(float4*)(&qs[c * PADP + d]) = aq;
            *(float4*)(&kn[c * PADP + d]) = ak;
            *(float4*)(&vb[c * PADP + d]) = av;
            *(float4*)(&g_v[(((size_t)b * Ll + l) * NHh + h) * 256 + d]) = av;
        }
    }
    if (t < CHh) bet[t] = g_beta[((size_t)b * Ll + l0 + t) * NHh + h];
    __syncthreads();

    int lane = t & 31;
    int wid = t >> 5;
    for (int r = wid; r < CHh; r += 8) {
        float sq = 0.f, sk = 0.f;
        for (int d = lane; d < 256; d += 32) {
            float a = qs[r * PADP + d]; sq += a * a;
            float c2 = kn[r * PADP + d]; sk += c2 * c2;
        }
        for (int o = 16; o; o >>= 1) {
            sq += __shfl_xor_sync(0xffffffffu, sq, o);
            sk += __shfl_xor_sync(0xffffffffu, sk, o);
        }
        if (!lane) { rsq[r] = rsqrtf(sq + 1e-6f); rsk[r] = rsqrtf(sk + 1e-6f); }
    }
    __syncthreads();

    for (int idx = t; idx < 32 * 64; idx += 256) {
        int c = idx >> 6;
        int d = (idx & 63) << 2;
        float4 qv = *(float4*)(&qs[c * PADP + d]);
        float4 kv = *(float4*)(&kn[c * PADP + d]);
        float4 vv = *(float4*)(&vb[c * PADP + d]);
        float rq = rsq[c], rk = rsk[c], bb2 = bet[c];
        qv.x *= rq; qv.y *= rq; qv.z *= rq; qv.w *= rq;
        kv.x *= rk; kv.y *= rk; kv.z *= rk; kv.w *= rk;
        vv.x *= bb2; vv.y *= bb2; vv.z *= bb2; vv.w *= bb2;
        *(float4*)(&qs[c * PADP + d]) = qv;
        *(float4*)(&kn[c * PADP + d]) = kv;
        *(float4*)(&vb[c * PADP + d]) = vv;
        *(float4*)(&g_qn[obase + c * 256 + d]) = qv;
        *(float4*)(&g_kn[obase + c * 256 + d]) = kv;
    }
    __syncthreads();

    {
        int ti = t >> 4;
        int tj = t & 15;
        const float* qA = &qs[ti * PADP];
        const float* qB = &qs[(ti + 16) * PADP];
        const float* kI0 = &kn[ti * PADP];
        const float* kI1 = &kn[(ti + 16) * PADP];
        const float* kJ0 = &kn[tj * PADP];
        const float* kJ1 = &kn[(tj + 16) * PADP];
        float dq00 = 0.f, dq01 = 0.f, dq10 = 0.f, dq11 = 0.f;
        float dk00 = 0.f, dk01 = 0.f, dk10 = 0.f, dk11 = 0.f;
#pragma unroll 4
        for (int d4 = 0; d4 < 64; d4++) {
            int d = d4 << 2;
            float4 a0 = *(const float4*)(&qA[d]);
            float4 a1 = *(const float4*)(&qB[d]);
            float4 b0 = *(const float4*)(&kJ0[d]);
            float4 b1 = *(const float4*)(&kJ1[d]);
            float4 c0 = *(const float4*)(&kI0[d]);
            float4 c1 = *(const float4*)(&kI1[d]);
            dq00 += a0.x * b0.x; dq00 += a0.y * b0.y; dq00 += a0.z * b0.z; dq00 += a0.w * b0.w;
            dq01 += a0.x * b1.x; dq01 += a0.y * b1.y; dq01 += a0.z * b1.z; dq01 += a0.w * b1.w;
            dq10 += a1.x * b0.x; dq10 += a1.y * b0.y; dq10 += a1.z * b0.z; dq10 += a1.w * b0.w;
            dq11 += a1.x * b1.x; dq11 += a1.y * b1.y; dq11 += a1.z * b1.z; dq11 += a1.w * b1.w;
            dk00 += c0.x * b0.x; dk00 += c0.y * b0.y; dk00 += c0.z * b0.z; dk00 += c0.w * b0.w;
            dk01 += c0.x * b1.x; dk01 += c0.y * b1.y; dk01 += c0.z * b1.z; dk01 += c0.w * b1.w;
            dk10 += c1.x * b0.x; dk10 += c1.y * b0.y; dk10 += c1.z * b0.z; dk10 += c1.w * b0.w;
            dk11 += c1.x * b1.x; dk11 += c1.y * b1.y; dk11 += c1.z * b1.z; dk11 += c1.w * b1.w;
        }
        size_t abase = ((((size_t)b * NHh + h) * NCc + n) << 10);
        int i0 = ti, i1 = ti + 16, j0 = tj, j1 = tj + 16;
        float bi0 = bet[i0], bi1 = bet[i1];
        Am[i0 * 32 + j0] = (j0 < i0) ? (-bi0 * dk00) : 0.f;
        Am[i0 * 32 + j1] = (j1 < i0) ? (-bi0 * dk01) : 0.f;
        Am[i1 * 32 + j0] = (j0 < i1) ? (-bi1 * dk10) : 0.f;
        Am[i1 * 32 + j1] = (j1 < i1) ? (-bi1 * dk11) : 0.f;
        g_attn[abase + i0 * 32 + j0] = (j0 <= i0) ? dq00 : 0.f;
        g_attn[abase + i0 * 32 + j1] = (j1 <= i0) ? dq01 : 0.f;
        g_attn[abase + i1 * 32 + j0] = (j0 <= i1) ? dq10 : 0.f;
        g_attn[abase + i1 * 32 + j1] = (j1 <= i1) ? dq11 : 0.f;
    }
    __syncthreads();

    if (t < 32) {
        Tm[t] = (t == 0) ? 1.f : 0.f;
        for (int i = 1; i < 32; i++) {
            float acc = (i == t) ? 1.f : 0.f;
            for (int m = 0; m < i; m++) acc += Am[i * 32 + m] * Tm[m * 33 + t];
            Tm[i * 33 + t] = acc;
        }
    }
    __syncthreads();

    {
        int d = t;
        float vbr[32], knr[32];
#pragma unroll
        for (int m = 0; m < 32; m++) {
            vbr[m] = vb[m * PADP + d];
            knr[m] = kn[m * PADP + d] * bet[m];
        }
#pragma unroll
        for (int r = 0; r < 32; r++) {
            float au = 0.f, aw = 0.f;
#pragma unroll
            for (int m = 0; m < 32; m++) {
                if (m <= r) {
                    float tv = Tm[r * 33 + m];
                    au += tv * vbr[m];
                    aw += tv * knr[m];
                }
            }
            g_u[obase + r * 256 + d] = au;
            g_w[obase + r * 256 + d] = aw;
        }
    }
}

// ---------------- serial chunk scan: 512 threads (R16-proven) ----------------
#define KST 272
__global__ __launch_bounds__(512) void scan_kernel() {
    float* smf = (float*)dynsm;
    float* S  = smf;
    float* qn = S + 4352;
    float* kn = qn + 8704;
    float* wS = kn + 8704;
    float* un = wS + 8704;
    float* uu = un + 544;
    float* at = uu + 512;

    int t = threadIdx.x;
    int s_idx = blockIdx.x & 15;
    int bh = blockIdx.x >> 4;
    int h = bh & 3;
    int b = bh >> 2;
    int j0 = s_idx * 16;

    for (int i = t; i < 4352; i += 512) S[i] = 0.f;
    __syncthreads();

    int j = t & 15;
    int c = t >> 4;

    for (int n = 0; n < NCc; n++) {
        size_t base = ((((size_t)b * NHh + h) * NCc + n) * CHh) * 256;
        for (int idx = t; idx < 32 * 64; idx += 512) {
            int cc = idx >> 6;
            int dq = (idx & 63) << 2;
            *(float4*)(&qn[cc * KST + dq]) = *(const float4*)(&g_qn[base + cc * 256 + dq]);
            *(float4*)(&kn[cc * KST + dq]) = *(const float4*)(&g_kn[base + cc * 256 + dq]);
            *(float4*)(&wS[cc * KST + dq]) = *(const float4*)(&g_w [base + cc * 256 + dq]);
        }
        uu[c * 16 + j] = g_u[base + c * 256 + j0 + j];
        size_t abase = ((((size_t)b * NHh + h) * NCc + n) << 10);
        for (int idx = t; idx < 1024; idx += 512) {
            int cc = idx >> 5;
            int cp = idx & 31;
            at[cc * 33 + cp] = g_attn[abase + idx];
        }
        __syncthreads();

        float a = uu[c * 16 + j];
        float o = 0.f;
        const float* wr = &wS[c * KST];
        const float* qr = &qn[c * KST];
#pragma unroll 8
        for (int d4 = 0; d4 < 64; d4++) {
            int d = d4 << 2;
            float4 wv = *(const float4*)(&wr[d]);
            float4 qv = *(const float4*)(&qr[d]);
            float s0 = S[(d + 0) * 17 + j];
            float s1 = S[(d + 1) * 17 + j];
            float s2 = S[(d + 2) * 17 + j];
            float s3 = S[(d + 3) * 17 + j];
            a -= wv.x * s0 + wv.y * s1 + wv.z * s2 + wv.w * s3;
            o += qv.x * s0 + qv.y * s1 + qv.z * s2 + qv.w * s3;
        }
        un[c * 17 + j] = a;
        __syncthreads();

        for (int cp = 0; cp <= c; cp++) o += at[c * 33 + cp] * un[cp * 17 + j];
        {
            int l = n * CHh + c;
            size_t r0 = (((size_t)b * Ll + l) * NHh + h) * 4 + 2;
            g_P [r0 * 256 + j0 + j] = o;
            g_Ph[r0 * 256 + j0 + j] = __float2half(o);
        }

#pragma unroll
        for (int blk = 0; blk < 2; blk++) {
            int d0 = c * 8 + blk * 4;
            float s0 = S[(d0 + 0) * 17 + j];
            float s1 = S[(d0 + 1) * 17 + j];
            float s2 = S[(d0 + 2) * 17 + j];
            float s3 = S[(d0 + 3) * 17 + j];
            for (int cc = 0; cc < 32; cc++) {
                float u = un[cc * 17 + j];
                float4 kv = *(const float4*)(&kn[cc * KST + d0]);
                s0 += kv.x * u; s1 += kv.y * u; s2 += kv.z * u; s3 += kv.w * u;
            }
            S[(d0 + 0) * 17 + j] = s0;
            S[(d0 + 1) * 17 + j] = s1;
            S[(d0 + 2) * 17 + j] = s2;
            S[(d0 + 3) * 17 + j] = s3;
        }
        __syncthreads();
    }
}

// ---------------- gW1 stat-block column sums ----------------
__global__ void ssum_kernel(const float* __restrict__ gW1) {
    int idx = blockIdx.x * 256 + threadIdx.x;
    int s12 = idx / GHh;
    int nn = idx % GHh;
    float a = 0.f;
    const float* base = gW1 + (size_t)(1024 + s12 * 256) * GHh + nn;
    for (int r = 0; r < 256; r++) a += base[(size_t)r * GHh];
    g_ssum[idx] = a;
}

// ---------------- gate finalize (reads hid1 from fused qkvlin; writes oh) ----------------
__global__ void gate_final_kernel(const float* __restrict__ gb1,
                                  const float* __restrict__ gW2,
                                  const float* __restrict__ gb2,
                                  const float* __restrict__ temp,
                                  const float* __restrict__ epsf,
                                  const float* __restrict__ onw) {
    __shared__ float mid[GHh];
    __shared__ float st[12];
    __shared__ float w4[4];
    __shared__ float red[256];
    __shared__ float rS[256], rQ[256], rM[256];
    __shared__ float Psm[1024];
    int row = blockIdx.x;
    int t = threadIdx.x;
    int h = row & 3;
    int bl = row >> 2;

    {
        int jb = t >> 6;
        int s = t & 63;
        const float* p = &g_P[((size_t)row * 4 + jb) << 8];
        float sm = 0.f, sq = 0.f, mx = -3.4e38f;
#pragma unroll
        for (int k = 0; k < 4; k++) {
            float v = p[s + 64 * k];
            Psm[jb * 256 + s + 64 * k] = v;
            sm += v; sq += v * v; mx = fmaxf(mx, v);
        }
        rS[t] = sm; rQ[t] = sq; rM[t] = mx;
        __syncthreads();
        for (int str = 32; str >= 1; str >>= 1) {
            if (s < str) {
                rS[t] += rS[t + str];
                rQ[t] += rQ[t + str];
                rM[t] = fmaxf(rM[t], rM[t + str]);
            }
            __syncthreads();
        }
        if (s == 0) {
            st[jb * 3 + 0] = rS[t] * (1.f / 256.f);
            st[jb * 3 + 1] = sqrtf(fmaxf(rQ[t] * (1.f / 256.f), 1e-8f));
            st[jb * 3 + 2] = rM[t];
        }
        __syncthreads();
    }

    for (int nn = t; nn < GHh; nn += 256) {
        float val = g_qkvlin[(size_t)bl * QKVW + 3072 + nn] + g_bpart[(size_t)row * GHh + nn] + gb1[nn];
#pragma unroll
        for (int s12 = 0; s12 < 12; s12++) val += st[s12] * g_ssum[s12 * GHh + nn];
        mid[nn] = 0.5f * val * (1.f + erff(val * 0.70710678118654752f));
    }
    __syncthreads();

    {
        int o = t & 3;
        float p = 0.f;
        for (int nidx = t >> 2; nidx < GHh; nidx += 64) p += mid[nidx] * gW2[nidx * 4 + o];
        red[t] = p;
    }
    __syncthreads();
    if (t < 4) {
        float lg = gb2[t];
        for (int g = 0; g < 64; g++) lg += red[g * 4 + t];
        red[t] = lg;
    }
    __syncthreads();
    if (t == 0) {
        float tc = fminf(fmaxf(temp[h], 0.2f), 10.f);
        float l0 = red[0] / tc, l1 = red[1] / tc, l2 = red[2] / tc, l3 = red[3] / tc;
        float mx = fmaxf(fmaxf(l0, l1), fmaxf(l2, l3));
        float e0 = expf(l0 - mx), e1 = expf(l1 - mx), e2 = expf(l2 - mx), e3 = expf(l3 - mx);
        float s = e0 + e1 + e2 + e3;
        float w0 = e0 / s, w1 = e1 / s, w2 = e2 / s, w3 = e3 / s;
        float f0 = fminf(fmaxf(epsf[h * 4 + 0], 1e-7f), 0.1f);
        float f1 = fminf(fmaxf(epsf[h * 4 + 1], 1e-7f), 0.1f);
        float f2 = fminf(fmaxf(epsf[h * 4 + 2], 1e-7f), 0.1f);
        float f3 = fminf(fmaxf(epsf[h * 4 + 3], 1e-7f), 0.1f);
        w0 = fmaxf(w0, f0); w1 = fmaxf(w1, f1); w2 = fmaxf(w2, f2); w3 = fmaxf(w3, f3);
        float s2 = w0 + w1 + w2 + w3;
        w4[0] = w0 / s2; w4[1] = w1 / s2; w4[2] = w2 / s2; w4[3] = w3 / s2;
    }
    __syncthreads();

    float od = 0.f;
#pragma unroll
    for (int jj = 0; jj < 4; jj++) od += w4[jj] * Psm[jj * 256 + t];
    red[t] = od * od;
    __syncthreads();
    for (int s = 128; s > 0; s >>= 1) {
        if (t < s) red[t] += red[t + s];
        __syncthreads();
    }
    float ms = red[0] * (1.f / 256.f);
    g_oh[(size_t)bl * HIDv + h * 256 + t] = __float2half(od * rsqrtf(ms + 1e-5f) * onw[t]);
}

// ---------------- host launcher ----------------
static const int SCAN_SMEM = 32576 * 4;

extern "C" void kernel_launch(void* const* d_in, const int* in_sizes, int n_in,
                              void* d_out, int out_size) {
    const float *x = 0, *Wq = 0, *Wk = 0, *Wv = 0, *Wb = 0, *qc = 0, *kc = 0, *vc = 0;
    const float *firs = 0, *firl = 0, *gW1 = 0, *gb1 = 0, *gW2 = 0, *gb2 = 0;
    const float *temp = 0, *epsf = 0, *onw = 0, *Wo = 0;
    int occ1M = 0, occ4k = 0, occ4 = 0;
    for (int i = 0; i < n_in; i++) {
        const float* p = (const float*)d_in[i];
        switch (in_sizes[i]) {
            case 2097152: x = p; break;
            case 1048576:
                if (occ1M == 0) Wq = p; else if (occ1M == 1) Wk = p;
                else if (occ1M == 2) Wv = p; else Wo = p;
                occ1M++; break;
            case 4096:
                if (occ4k == 0) Wb = p; else if (occ4k == 1) qc = p;
                else if (occ4k == 2) kc = p; else vc = p;
                occ4k++; break;
            case 2621440: gW1 = p; break;
            case 512:     gb1 = p; break;
            case 2048:    gW2 = p; break;
            case 4:       if (occ4 == 0) gb2 = p; else temp = p; occ4++; break;
            case 16:      epsf = p; break;
            case 256:     onw = p; break;
            case 3072:    firs = p; break;
            case 31744:   firl = p; break;
            default: break;
        }
    }

    float *p_qkvlin, *p_bpart;
    cudaGetSymbolAddress((void**)&p_qkvlin, g_qkvlin);
    cudaGetSymbolAddress((void**)&p_bpart, g_bpart);

    __half *xh, *Ph, *oh, *Wqkvh, *Woh, *g1bh;
    cudaGetSymbolAddress((void**)&xh, g_xh);
    cudaGetSymbolAddress((void**)&Ph, g_Ph);
    cudaGetSymbolAddress((void**)&oh, g_oh);
    cudaGetSymbolAddress((void**)&Wqkvh, g_Wqkvh);
    cudaGetSymbolAddress((void**)&Woh, g_Woh);
    cudaGetSymbolAddress((void**)&g1bh, g_g1bh);

    cudaFuncSetAttribute(delta_pre_kernel, cudaFuncAttributeMaxDynamicSharedMemorySize, PRE_SMEM);
    cudaFuncSetAttribute(scan_kernel, cudaFuncAttributeMaxDynamicSharedMemorySize, SCAN_SMEM);
    cudaFuncSetAttribute(gemm_fp16, cudaFuncAttributeMaxDynamicSharedMemorySize, GEMM_SMEM);
    cudaFuncSetAttribute(fir_tiled_kernel, cudaFuncAttributeMaxDynamicSharedMemorySize, FIR_SMEM);

    const size_t W1M = (size_t)1024 * 1024;

    // single stream; launch #4 = merged QKV+hid1 GEMM (profiled)
    beta_xh_kernel<<<256, 256>>>(x, Wb);                                          // 1
    htrans4_kernel<<<dim3(32, 32, 4), 256>>>(Wq, Wk, Wv, Wo,
        Wqkvh, Wqkvh + W1M, Wqkvh + 2 * W1M, Woh);                                // 2
    htrans2_kernel<<<dim3(16, 32, 2), 256>>>(gW1, gW1 + (size_t)4096 * 512,
                                             Wqkvh + 3 * W1M, g1bh, 1024, 512);   // 3 (g1a -> fused W)
    gemm_fp16<<<dim3(14, 16), 256, GEMM_SMEM>>>(xh, Wqkvh, p_qkvlin, 2048, QKVW, 1024);  // 4 <- profiled
    ssum_kernel<<<24, 256>>>(gW1);                                                // 5
    delta_pre_kernel<<<256, 256, PRE_SMEM>>>(qc, kc, vc);                         // 6
    scan_kernel<<<128, 512, SCAN_SMEM>>>();                                       // 7
    fir_tiled_kernel<<<512, 256, FIR_SMEM>>>(firs, firl);                         // 8
    gemm_fp16<<<dim3(2, 64), 256, GEMM_SMEM>>>(Ph, g1bh, p_bpart, 8192, 512, 1024);       // 9
    gate_final_kernel<<<8192, 256>>>(gb1, gW2, gb2, temp, epsf, onw);             // 10
    gemm_fp16<<<dim3(4, 16), 256, GEMM_SMEM>>>(oh, Woh, (float*)d_out, 2048, 1024, 1024); // 11
}